// round 1
// baseline (speedup 1.0000x reference)
#include <cuda_runtime.h>

// Problem dims
#define NB 1000
#define NI 784
#define NR 256
#define NO 10

#define ALPHA 0.8f
#define KAPPA 0.8f

// ---------------- scratch (__device__ globals; no allocation) ----------------
__device__ float g_vpre[NB * NR];   // x@w_in.T + z@w_rec_eff.T  (split-K atomic accum)
__device__ float g_kL  [NB * NR];   // KAPPA * L
__device__ float g_Lh  [NB * NR];   // L * h
__device__ float g_Fazn[NB * NR];   // Faz*ALPHA + z(old)
__device__ float g_Fkzn[NB * NR];   // Fkz*KAPPA + z_new
__device__ float g_Faxn[NB * NI];   // Fax*ALPHA + x
__device__ float g_err [NB * NO];   // yo - yt

// ---------------- init: zero accumulators ----------------
__global__ void k_init(float* __restrict__ gwrec, float* __restrict__ gwout) {
    int idx = blockIdx.x * blockDim.x + threadIdx.x;
    int stride = gridDim.x * blockDim.x;
    for (int i = idx; i < NB * NR; i += stride) g_vpre[i] = 0.f;
    for (int i = idx; i < NR * NR; i += stride) gwrec[i] = 0.f;
    for (int i = idx; i < NO * NR; i += stride) gwout[i] = 0.f;
}

// ---------------- GEMM: g_vpre[b,r] = sum_k A[b,k] * W[r,k] ----------------
// A = [x | z]  (K = 784 + 256 = 1040),  W = [w_in | w_rec(diag zeroed)]
// 64x64 tile, BK=16, 256 threads (4x4 micro-tile), split-K = 2 (k<512 / k>=512)
__global__ void k_gemm(const float* __restrict__ x, const float* __restrict__ z,
                       const float* __restrict__ w_in, const float* __restrict__ w_rec) {
    __shared__ float As[16][68];
    __shared__ float Ws[16][68];
    const int row0 = blockIdx.x * 64;   // batch tile
    const int col0 = blockIdx.y * 64;   // rec-unit tile
    const int split = blockIdx.z;
    const int tid = threadIdx.x;
    const int tr = tid >> 4, tc = tid & 15;

    const int k_begin = split ? 512 : 0;
    const int k_end   = split ? 1040 : 512;

    float acc[4][4];
#pragma unroll
    for (int i = 0; i < 4; i++)
#pragma unroll
        for (int j = 0; j < 4; j++) acc[i][j] = 0.f;

    for (int kb = k_begin; kb < k_end; kb += 16) {
#pragma unroll
        for (int l = 0; l < 4; l++) {
            int idx = tid + l * 256;
            int kk = idx & 15;
            int m  = idx >> 4;          // 0..63
            int k  = kb + kk;
            // A tile (coalesced in k)
            int b = row0 + m;
            float av = 0.f;
            if (b < NB) av = (k < NI) ? x[b * NI + k] : z[b * NR + (k - NI)];
            As[kk][m] = av;
            // W tile (coalesced in k)
            int r = col0 + m;
            float wv;
            if (k < NI) {
                wv = w_in[r * NI + k];
            } else {
                int kr = k - NI;
                wv = (kr == r) ? 0.f : w_rec[r * NR + kr];
            }
            Ws[kk][m] = wv;
        }
        __syncthreads();
#pragma unroll
        for (int kk = 0; kk < 16; kk++) {
            float ra[4], rw[4];
#pragma unroll
            for (int i = 0; i < 4; i++) ra[i] = As[kk][tr * 4 + i];
#pragma unroll
            for (int j = 0; j < 4; j++) rw[j] = Ws[kk][tc * 4 + j];
#pragma unroll
            for (int i = 0; i < 4; i++)
#pragma unroll
                for (int j = 0; j < 4; j++)
                    acc[i][j] = fmaf(ra[i], rw[j], acc[i][j]);
        }
        __syncthreads();
    }
#pragma unroll
    for (int i = 0; i < 4; i++) {
        int b = row0 + tr * 4 + i;
        if (b < NB) {
#pragma unroll
            for (int j = 0; j < 4; j++)
                atomicAdd(&g_vpre[b * NR + col0 + tc * 4 + j], acc[i][j]);
        }
    }
}

// ---------------- per-batch fused step ----------------
// v_new, z_new, h, vo_new, softmax -> yo (out), err, L, traces
__global__ void k_step(const float* __restrict__ v, const float* __restrict__ vo,
                       const float* __restrict__ z, const float* __restrict__ Faz,
                       const float* __restrict__ Fkz, const float* __restrict__ Fax,
                       const float* __restrict__ x, const float* __restrict__ w_out,
                       const float* __restrict__ yt, float* __restrict__ yo_out) {
    const int b = blockIdx.x;
    const int r = threadIdx.x;
    __shared__ float s_zn[NR];
    __shared__ float s_tmp[NO];

    const int ir = b * NR + r;
    const float zb = z[ir];
    const float vn = g_vpre[ir] + ALPHA * v[ir] * (1.f - zb);
    const float zn = (vn > 1.f) ? 1.f : 0.f;
    s_zn[r] = zn;
    const float h = fmaxf(0.f, 1.f - fabsf(vn - 1.f));  // GAMMA=1, THR=1
    g_Fazn[ir] = ALPHA * Faz[ir] + zb;   // uses old z
    g_Fkzn[ir] = KAPPA * Fkz[ir] + zn;   // uses new z
    __syncthreads();

    if (r < NO) {
        float a = KAPPA * vo[b * NO + r];
#pragma unroll 8
        for (int j = 0; j < NR; j++) a = fmaf(s_zn[j], w_out[r * NR + j], a);
        s_tmp[r] = a;   // vo_new[o]
    }
    __syncthreads();

    if (r == 0) {
        float m = s_tmp[0];
#pragma unroll
        for (int o = 1; o < NO; o++) m = fmaxf(m, s_tmp[o]);
        float e[NO];
        float s = 0.f;
#pragma unroll
        for (int o = 0; o < NO; o++) { e[o] = expf(s_tmp[o] - m); s += e[o]; }
        const float inv = 1.f / s;
#pragma unroll
        for (int o = 0; o < NO; o++) {
            const float yo = e[o] * inv;
            yo_out[b * NO + o] = yo;
            const float er = yo - yt[b * NO + o];
            s_tmp[o] = er;
            g_err[b * NO + o] = er;
        }
    }
    __syncthreads();

    float L = 0.f;
#pragma unroll
    for (int o = 0; o < NO; o++) L = fmaf(s_tmp[o], w_out[o * NR + r], L);
    g_kL[ir] = KAPPA * L;
    g_Lh[ir] = L * h;

    for (int j = r; j < NI; j += NR)
        g_Faxn[b * NI + j] = ALPHA * Fax[b * NI + j] + x[b * NI + j];
}

// ---------------- gw_out[o,r] = sum_b err[b,o] * Fkz_new[b,r] ----------------
__global__ void k_gwout(float* __restrict__ gwout) {
    const int chunk = blockIdx.x;        // 8 chunks of 125 batches
    const int r = threadIdx.x;           // 256
    __shared__ float s_err[125 * NO];
    for (int t = r; t < 125 * NO; t += 256) s_err[t] = g_err[chunk * 125 * NO + t];
    __syncthreads();
    float acc[NO];
#pragma unroll
    for (int o = 0; o < NO; o++) acc[o] = 0.f;
    const int b0 = chunk * 125;
    for (int bb = 0; bb < 125; bb++) {
        const float f = g_Fkzn[(b0 + bb) * NR + r];
#pragma unroll
        for (int o = 0; o < NO; o++) acc[o] = fmaf(s_err[bb * NO + o], f, acc[o]);
    }
#pragma unroll
    for (int o = 0; o < NO; o++) atomicAdd(&gwout[o * NR + r], acc[o]);
}

// ---------------- gw_rec[i,j] = sum_b kL[b,i]*Fke_rec[b,i,j] + Lh[b,i]*Faz_new[b,j] ----------------
// grid: (i=256, half=2) ; 256 threads over j ; b split in halves of 500, atomic combine
__global__ void k_gwrec(const float* __restrict__ Fke_rec, float* __restrict__ gwrec) {
    const int i = blockIdx.x;
    const int half = blockIdx.y;
    const int j = threadIdx.x;
    const int b0 = half * 500;
    __shared__ float s_kL[500], s_Lh[500];
    for (int t = j; t < 500; t += 256) {
        s_kL[t] = g_kL[(b0 + t) * NR + i];
        s_Lh[t] = g_Lh[(b0 + t) * NR + i];
    }
    __syncthreads();
    const float* fke = Fke_rec + (size_t)b0 * NR * NR + (size_t)i * NR + j;
    const float* faz = g_Fazn + b0 * NR + j;
    float acc = 0.f;
#pragma unroll 8
    for (int bb = 0; bb < 500; bb++)
        acc += s_kL[bb] * fke[(size_t)bb * (NR * NR)] + s_Lh[bb] * faz[bb * NR];
    atomicAdd(&gwrec[i * NR + j], acc);
}

// ---------------- gw_in[i,j] = sum_b kL[b,i]*Fke_in[b,i,j] + Lh[b,i]*Fax_new[b,j] ----------------
// grid: (i=256, jc=4) ; 256 threads over j ; full b loop (no atomics)
__global__ void k_gwin(const float* __restrict__ Fke_in, float* __restrict__ gwin) {
    const int i = blockIdx.x;
    const int j = blockIdx.y * 256 + threadIdx.x;
    __shared__ float s_kL[NB], s_Lh[NB];
    for (int t = threadIdx.x; t < NB; t += 256) {
        s_kL[t] = g_kL[t * NR + i];
        s_Lh[t] = g_Lh[t * NR + i];
    }
    __syncthreads();
    if (j >= NI) return;
    const float* fke = Fke_in + (size_t)i * NI + j;
    const float* fax = g_Faxn + j;
    float acc = 0.f;
#pragma unroll 8
    for (int b = 0; b < NB; b++)
        acc += s_kL[b] * fke[(size_t)b * (NR * NI)] + s_Lh[b] * fax[(size_t)b * NI];
    gwin[i * NI + j] = acc;
}

// ---------------- launch ----------------
extern "C" void kernel_launch(void* const* d_in, const int* in_sizes, int n_in,
                              void* d_out, int out_size) {
    const float* x       = (const float*)d_in[0];
    // d_in[1] = do_training (int32, always the training path in this dataset)
    const float* yt      = (const float*)d_in[2];
    const float* w_in    = (const float*)d_in[3];
    const float* w_rec   = (const float*)d_in[4];
    const float* w_out   = (const float*)d_in[5];
    const float* v       = (const float*)d_in[6];
    const float* vo      = (const float*)d_in[7];
    const float* z       = (const float*)d_in[8];
    const float* Faz     = (const float*)d_in[9];
    const float* Fkz     = (const float*)d_in[10];
    const float* Fax     = (const float*)d_in[11];
    const float* Fke_rec = (const float*)d_in[12];
    const float* Fke_in  = (const float*)d_in[13];

    float* out     = (float*)d_out;
    float* yo_o    = out;                    // [1000,10]   -> 10000
    float* gwin_o  = out + NB * NO;          // [256,784]   -> 200704
    float* gwrec_o = gwin_o + NR * NI;       // [256,256]   -> 65536
    float* gwout_o = gwrec_o + NR * NR;      // [10,256]    -> 2560

    k_init<<<256, 256>>>(gwrec_o, gwout_o);
    k_gemm<<<dim3(16, 4, 2), 256>>>(x, z, w_in, w_rec);
    k_step<<<NB, NR>>>(v, vo, z, Faz, Fkz, Fax, x, w_out, yt, yo_o);
    k_gwout<<<8, 256>>>(gwout_o);
    k_gwrec<<<dim3(256, 2), 256>>>(Fke_rec, gwrec_o);
    k_gwin<<<dim3(256, 4), 256>>>(Fke_in, gwin_o);
}

// round 2
// speedup vs baseline: 1.0678x; 1.0678x over previous
#include <cuda_runtime.h>

// Problem dims
#define NB 1000
#define NI 784
#define NR 256
#define NO 10

#define ALPHA 0.8f
#define KAPPA 0.8f

// ---------------- scratch (__device__ globals; no allocation) ----------------
__device__ float g_vpre[NB * NR];   // x@w_in.T + z@w_rec_eff.T  (split-K atomic accum)
__device__ float g_kL  [NB * NR];   // KAPPA * L
__device__ float g_Lh  [NB * NR];   // L * h
__device__ float g_Fazn[NB * NR];   // Faz*ALPHA + z(old)
__device__ float g_Fkzn[NB * NR];   // Fkz*KAPPA + z_new
__device__ float g_Faxn[NB * NI];   // Fax*ALPHA + x
__device__ float g_err [NB * NO];   // yo - yt

// ---------------- init: zero accumulators + outputs that get atomics ----------------
__global__ void k_init(float* __restrict__ gwin, float* __restrict__ gwrec,
                       float* __restrict__ gwout) {
    int idx = blockIdx.x * blockDim.x + threadIdx.x;
    int stride = gridDim.x * blockDim.x;
    for (int i = idx; i < NB * NR; i += stride) g_vpre[i] = 0.f;
    for (int i = idx; i < NR * NI; i += stride) gwin[i] = 0.f;
    for (int i = idx; i < NR * NR; i += stride) gwrec[i] = 0.f;
    for (int i = idx; i < NO * NR; i += stride) gwout[i] = 0.f;
}

// ---------------- GEMM: g_vpre[b,r] = sum_k A[b,k] * W[r,k] ----------------
// A = [x | z]  (K = 784 + 256 = 1040),  W = [w_in | w_rec(diag zeroed)]
__global__ void k_gemm(const float* __restrict__ x, const float* __restrict__ z,
                       const float* __restrict__ w_in, const float* __restrict__ w_rec) {
    __shared__ float As[16][68];
    __shared__ float Ws[16][68];
    const int row0 = blockIdx.x * 64;   // batch tile
    const int col0 = blockIdx.y * 64;   // rec-unit tile
    const int split = blockIdx.z;
    const int tid = threadIdx.x;
    const int tr = tid >> 4, tc = tid & 15;

    const int k_begin = split ? 512 : 0;
    const int k_end   = split ? 1040 : 512;

    float acc[4][4];
#pragma unroll
    for (int i = 0; i < 4; i++)
#pragma unroll
        for (int j = 0; j < 4; j++) acc[i][j] = 0.f;

    for (int kb = k_begin; kb < k_end; kb += 16) {
#pragma unroll
        for (int l = 0; l < 4; l++) {
            int idx = tid + l * 256;
            int kk = idx & 15;
            int m  = idx >> 4;          // 0..63
            int k  = kb + kk;
            int b = row0 + m;
            float av = 0.f;
            if (b < NB) av = (k < NI) ? x[b * NI + k] : z[b * NR + (k - NI)];
            As[kk][m] = av;
            int r = col0 + m;
            float wv;
            if (k < NI) {
                wv = w_in[r * NI + k];
            } else {
                int kr = k - NI;
                wv = (kr == r) ? 0.f : w_rec[r * NR + kr];
            }
            Ws[kk][m] = wv;
        }
        __syncthreads();
#pragma unroll
        for (int kk = 0; kk < 16; kk++) {
            float ra[4], rw[4];
#pragma unroll
            for (int i = 0; i < 4; i++) ra[i] = As[kk][tr * 4 + i];
#pragma unroll
            for (int j = 0; j < 4; j++) rw[j] = Ws[kk][tc * 4 + j];
#pragma unroll
            for (int i = 0; i < 4; i++)
#pragma unroll
                for (int j = 0; j < 4; j++)
                    acc[i][j] = fmaf(ra[i], rw[j], acc[i][j]);
        }
        __syncthreads();
    }
#pragma unroll
    for (int i = 0; i < 4; i++) {
        int b = row0 + tr * 4 + i;
        if (b < NB) {
#pragma unroll
            for (int j = 0; j < 4; j++)
                atomicAdd(&g_vpre[b * NR + col0 + tc * 4 + j], acc[i][j]);
        }
    }
}

// ---------------- per-batch fused step ----------------
__global__ void k_step(const float* __restrict__ v, const float* __restrict__ vo,
                       const float* __restrict__ z, const float* __restrict__ Faz,
                       const float* __restrict__ Fkz, const float* __restrict__ Fax,
                       const float* __restrict__ x, const float* __restrict__ w_out,
                       const float* __restrict__ yt, float* __restrict__ yo_out) {
    const int b = blockIdx.x;
    const int r = threadIdx.x;
    __shared__ float s_zn[NR];
    __shared__ float s_tmp[NO];

    const int ir = b * NR + r;
    const float zb = z[ir];
    const float vn = g_vpre[ir] + ALPHA * v[ir] * (1.f - zb);
    const float zn = (vn > 1.f) ? 1.f : 0.f;
    s_zn[r] = zn;
    const float h = fmaxf(0.f, 1.f - fabsf(vn - 1.f));  // GAMMA=1, THR=1
    g_Fazn[ir] = ALPHA * Faz[ir] + zb;   // uses old z
    g_Fkzn[ir] = KAPPA * Fkz[ir] + zn;   // uses new z
    __syncthreads();

    if (r < NO) {
        float a = KAPPA * vo[b * NO + r];
#pragma unroll 8
        for (int j = 0; j < NR; j++) a = fmaf(s_zn[j], w_out[r * NR + j], a);
        s_tmp[r] = a;   // vo_new[o]
    }
    __syncthreads();

    if (r == 0) {
        float m = s_tmp[0];
#pragma unroll
        for (int o = 1; o < NO; o++) m = fmaxf(m, s_tmp[o]);
        float e[NO];
        float s = 0.f;
#pragma unroll
        for (int o = 0; o < NO; o++) { e[o] = expf(s_tmp[o] - m); s += e[o]; }
        const float inv = 1.f / s;
#pragma unroll
        for (int o = 0; o < NO; o++) {
            const float yo = e[o] * inv;
            yo_out[b * NO + o] = yo;
            const float er = yo - yt[b * NO + o];
            s_tmp[o] = er;
            g_err[b * NO + o] = er;
        }
    }
    __syncthreads();

    float L = 0.f;
#pragma unroll
    for (int o = 0; o < NO; o++) L = fmaf(s_tmp[o], w_out[o * NR + r], L);
    g_kL[ir] = KAPPA * L;
    g_Lh[ir] = L * h;

    for (int j = r; j < NI; j += NR)
        g_Faxn[b * NI + j] = ALPHA * Fax[b * NI + j] + x[b * NI + j];
}

// ---------------- rank-term GEMM: O[i,jj] = sum_b Lh[b,i] * C[b,jj] ----------------
// C = [Faxn (784) | Fazn (256)], O split-written into gwin / gwrec (atomic, split-K=2)
__global__ void k_outer(float* __restrict__ gwin, float* __restrict__ gwrec) {
    __shared__ float As[16][68];   // As[kk][i_local]   (Lh^T)
    __shared__ float Bs[16][68];   // Bs[kk][j_local]
    const int i0 = blockIdx.x * 64;        // 4 tiles over i (256)
    const int j0 = blockIdx.y * 64;        // 17 tiles over jj (1040)
    const int kb0 = blockIdx.z * 500;
    const int kb1 = kb0 + 500;
    const int tid = threadIdx.x;
    const int tr = tid >> 4, tc = tid & 15;

    float acc[4][4];
#pragma unroll
    for (int i = 0; i < 4; i++)
#pragma unroll
        for (int j = 0; j < 4; j++) acc[i][j] = 0.f;

    for (int kb = kb0; kb < kb1; kb += 16) {
#pragma unroll
        for (int l = 0; l < 4; l++) {
            int idx = tid + l * 256;
            int kk = idx & 15;
            int m  = idx >> 4;
            int k  = kb + kk;
            As[kk][m] = (k < kb1) ? g_Lh[k * NR + i0 + m] : 0.f;
            int jj = j0 + m;
            float bv = 0.f;
            if (k < kb1 && jj < 1040)
                bv = (jj < NI) ? g_Faxn[k * NI + jj] : g_Fazn[k * NR + (jj - NI)];
            Bs[kk][m] = bv;
        }
        __syncthreads();
#pragma unroll
        for (int kk = 0; kk < 16; kk++) {
            float ra[4], rb[4];
#pragma unroll
            for (int i = 0; i < 4; i++) ra[i] = As[kk][tr * 4 + i];
#pragma unroll
            for (int j = 0; j < 4; j++) rb[j] = Bs[kk][tc * 4 + j];
#pragma unroll
            for (int i = 0; i < 4; i++)
#pragma unroll
                for (int j = 0; j < 4; j++)
                    acc[i][j] = fmaf(ra[i], rb[j], acc[i][j]);
        }
        __syncthreads();
    }
#pragma unroll
    for (int i = 0; i < 4; i++) {
        int row = i0 + tr * 4 + i;
#pragma unroll
        for (int j = 0; j < 4; j++) {
            int jj = j0 + tc * 4 + j;
            if (jj < NI)            atomicAdd(&gwin[row * NI + jj], acc[i][j]);
            else if (jj < NI + NR)  atomicAdd(&gwrec[row * NR + (jj - NI)], acc[i][j]);
        }
    }
}

// ---------------- gw_out[o,r] = sum_b err[b,o] * Fkz_new[b,r] ----------------
__global__ void k_gwout(float* __restrict__ gwout) {
    const int chunk = blockIdx.x;        // 50 chunks of 20 batches
    const int r = threadIdx.x;           // 256
    const int b0 = chunk * 20;
    __shared__ float s_err[20 * NO];
    for (int t = r; t < 20 * NO; t += 256) s_err[t] = g_err[b0 * NO + t];
    __syncthreads();
    float acc[NO];
#pragma unroll
    for (int o = 0; o < NO; o++) acc[o] = 0.f;
    for (int bb = 0; bb < 20; bb++) {
        const float f = g_Fkzn[(b0 + bb) * NR + r];
#pragma unroll
        for (int o = 0; o < NO; o++) acc[o] = fmaf(s_err[bb * NO + o], f, acc[o]);
    }
#pragma unroll
    for (int o = 0; o < NO; o++) atomicAdd(&gwout[o * NR + r], acc[o]);
}

// ---------------- streaming: gwrec[i,j] += sum_b kL[b,i] * Fke_rec[b,i,j] ----------------
// grid (i=256, bs=4), block 64 threads; each thread one float4 column, 250 batches
__global__ void k_gwrec_stream(const float* __restrict__ Fke_rec, float* __restrict__ gwrec) {
    const int i  = blockIdx.x;
    const int b0 = blockIdx.y * 250;
    const int jv = threadIdx.x;          // 0..63  (j = 4*jv .. 4*jv+3)
    __shared__ float s_kL[250];
    for (int t = jv; t < 250; t += 64) s_kL[t] = g_kL[(b0 + t) * NR + i];
    __syncthreads();

    const float4* fke = (const float4*)(Fke_rec + ((size_t)b0 * NR + i) * NR) + jv;
    const size_t stride = (size_t)NR * NR / 4;   // float4 stride per batch
    float4 a0 = make_float4(0.f, 0.f, 0.f, 0.f);
    float4 a1 = make_float4(0.f, 0.f, 0.f, 0.f);
#pragma unroll 2
    for (int bb = 0; bb < 250; bb += 2) {
        float4 f0 = fke[(size_t)bb * stride];
        float4 f1 = fke[(size_t)(bb + 1) * stride];
        float c0 = s_kL[bb], c1 = s_kL[bb + 1];
        a0.x = fmaf(c0, f0.x, a0.x); a0.y = fmaf(c0, f0.y, a0.y);
        a0.z = fmaf(c0, f0.z, a0.z); a0.w = fmaf(c0, f0.w, a0.w);
        a1.x = fmaf(c1, f1.x, a1.x); a1.y = fmaf(c1, f1.y, a1.y);
        a1.z = fmaf(c1, f1.z, a1.z); a1.w = fmaf(c1, f1.w, a1.w);
    }
    float* dst = gwrec + i * NR + jv * 4;
    atomicAdd(dst + 0, a0.x + a1.x);
    atomicAdd(dst + 1, a0.y + a1.y);
    atomicAdd(dst + 2, a0.z + a1.z);
    atomicAdd(dst + 3, a0.w + a1.w);
}

// ---------------- streaming: gwin[i,j] += sum_b kL[b,i] * Fke_in[b,i,j] ----------------
// grid (i=256, bs=4), block 224 threads (196 active float4 columns), 250 batches
__global__ void k_gwin_stream(const float* __restrict__ Fke_in, float* __restrict__ gwin) {
    const int i  = blockIdx.x;
    const int b0 = blockIdx.y * 250;
    const int lane = threadIdx.x;        // 0..223, active < 196
    __shared__ float s_kL[250];
    for (int t = lane; t < 250; t += 224) s_kL[t] = g_kL[(b0 + t) * NR + i];
    __syncthreads();
    if (lane >= 196) return;

    const float4* fke = (const float4*)(Fke_in + ((size_t)b0 * NR + i) * NI) + lane;
    const size_t stride = (size_t)NR * NI / 4;   // float4 stride per batch
    float4 a0 = make_float4(0.f, 0.f, 0.f, 0.f);
    float4 a1 = make_float4(0.f, 0.f, 0.f, 0.f);
#pragma unroll 2
    for (int bb = 0; bb < 250; bb += 2) {
        float4 f0 = fke[(size_t)bb * stride];
        float4 f1 = fke[(size_t)(bb + 1) * stride];
        float c0 = s_kL[bb], c1 = s_kL[bb + 1];
        a0.x = fmaf(c0, f0.x, a0.x); a0.y = fmaf(c0, f0.y, a0.y);
        a0.z = fmaf(c0, f0.z, a0.z); a0.w = fmaf(c0, f0.w, a0.w);
        a1.x = fmaf(c1, f1.x, a1.x); a1.y = fmaf(c1, f1.y, a1.y);
        a1.z = fmaf(c1, f1.z, a1.z); a1.w = fmaf(c1, f1.w, a1.w);
    }
    float* dst = gwin + i * NI + lane * 4;
    atomicAdd(dst + 0, a0.x + a1.x);
    atomicAdd(dst + 1, a0.y + a1.y);
    atomicAdd(dst + 2, a0.z + a1.z);
    atomicAdd(dst + 3, a0.w + a1.w);
}

// ---------------- launch ----------------
extern "C" void kernel_launch(void* const* d_in, const int* in_sizes, int n_in,
                              void* d_out, int out_size) {
    const float* x       = (const float*)d_in[0];
    const float* yt      = (const float*)d_in[2];
    const float* w_in    = (const float*)d_in[3];
    const float* w_rec   = (const float*)d_in[4];
    const float* w_out   = (const float*)d_in[5];
    const float* v       = (const float*)d_in[6];
    const float* vo      = (const float*)d_in[7];
    const float* z       = (const float*)d_in[8];
    const float* Faz     = (const float*)d_in[9];
    const float* Fkz     = (const float*)d_in[10];
    const float* Fax     = (const float*)d_in[11];
    const float* Fke_rec = (const float*)d_in[12];
    const float* Fke_in  = (const float*)d_in[13];

    float* out     = (float*)d_out;
    float* yo_o    = out;                    // [1000,10]
    float* gwin_o  = out + NB * NO;          // [256,784]
    float* gwrec_o = gwin_o + NR * NI;       // [256,256]
    float* gwout_o = gwrec_o + NR * NR;      // [10,256]

    k_init<<<512, 256>>>(gwin_o, gwrec_o, gwout_o);
    k_gemm<<<dim3(16, 4, 2), 256>>>(x, z, w_in, w_rec);
    k_step<<<NB, NR>>>(v, vo, z, Faz, Fkz, Fax, x, w_out, yt, yo_o);
    k_outer<<<dim3(4, 17, 2), 256>>>(gwin_o, gwrec_o);
    k_gwout<<<50, 256>>>(gwout_o);
    k_gwrec_stream<<<dim3(256, 4), 64>>>(Fke_rec, gwrec_o);
    k_gwin_stream<<<dim3(256, 4), 224>>>(Fke_in, gwin_o);
}

// round 3
// speedup vs baseline: 1.1929x; 1.1172x over previous
#include <cuda_runtime.h>

// Problem dims
#define NB 1000
#define NI 784
#define NR 256
#define NO 10

#define ALPHA 0.8f
#define KAPPA 0.8f

// ---------------- scratch (__device__ globals; no allocation) ----------------
__device__ float g_vpre[NB * NR];
__device__ float g_kL  [NB * NR];
__device__ float g_Lh  [NB * NR];
__device__ float g_Fazn[NB * NR];
__device__ float g_Fkzn[NB * NR];
__device__ float g_Faxn[NB * NI];
__device__ float g_err [NB * NO];

// ---------------- init: zero accumulators + atomic-target outputs ----------------
__global__ void k_init(float* __restrict__ gwin, float* __restrict__ gwrec,
                       float* __restrict__ gwout) {
    int idx = blockIdx.x * blockDim.x + threadIdx.x;
    int stride = gridDim.x * blockDim.x;
    for (int i = idx; i < NB * NR; i += stride) g_vpre[i] = 0.f;
    for (int i = idx; i < NR * NI; i += stride) gwin[i] = 0.f;
    for (int i = idx; i < NR * NR; i += stride) gwrec[i] = 0.f;
    for (int i = idx; i < NO * NR; i += stride) gwout[i] = 0.f;
}

// ---------------- GEMM: g_vpre[b,r] = sum_k A[b,k] * W[r,k] ----------------
// A = [x | z]  (K = 1040),  W = [w_in | w_rec(diag zeroed)]
// sources are contiguous in k -> loader indexes k with low bits (coalesced at sector granularity)
__global__ void k_gemm(const float* __restrict__ x, const float* __restrict__ z,
                       const float* __restrict__ w_in, const float* __restrict__ w_rec) {
    __shared__ float As[16][68];
    __shared__ float Ws[16][68];
    const int row0 = blockIdx.x * 64;
    const int col0 = blockIdx.y * 64;
    const int split = blockIdx.z;
    const int tid = threadIdx.x;
    const int tr = tid >> 4, tc = tid & 15;

    const int k_begin = split ? 512 : 0;
    const int k_end   = split ? 1040 : 512;

    float acc[4][4];
#pragma unroll
    for (int i = 0; i < 4; i++)
#pragma unroll
        for (int j = 0; j < 4; j++) acc[i][j] = 0.f;

    for (int kb = k_begin; kb < k_end; kb += 16) {
#pragma unroll
        for (int l = 0; l < 4; l++) {
            int idx = tid + l * 256;
            int kk = idx & 15;
            int m  = idx >> 4;
            int k  = kb + kk;
            int b = row0 + m;
            float av = 0.f;
            if (b < NB) av = (k < NI) ? x[b * NI + k] : z[b * NR + (k - NI)];
            As[kk][m] = av;
            int r = col0 + m;
            float wv;
            if (k < NI) {
                wv = w_in[r * NI + k];
            } else {
                int kr = k - NI;
                wv = (kr == r) ? 0.f : w_rec[r * NR + kr];
            }
            Ws[kk][m] = wv;
        }
        __syncthreads();
#pragma unroll
        for (int kk = 0; kk < 16; kk++) {
            float ra[4], rw[4];
#pragma unroll
            for (int i = 0; i < 4; i++) ra[i] = As[kk][tr * 4 + i];
#pragma unroll
            for (int j = 0; j < 4; j++) rw[j] = Ws[kk][tc * 4 + j];
#pragma unroll
            for (int i = 0; i < 4; i++)
#pragma unroll
                for (int j = 0; j < 4; j++)
                    acc[i][j] = fmaf(ra[i], rw[j], acc[i][j]);
        }
        __syncthreads();
    }
#pragma unroll
    for (int i = 0; i < 4; i++) {
        int b = row0 + tr * 4 + i;
        if (b < NB) {
#pragma unroll
            for (int j = 0; j < 4; j++)
                atomicAdd(&g_vpre[b * NR + col0 + tc * 4 + j], acc[i][j]);
        }
    }
}

// ---------------- per-batch fused step ----------------
__global__ void k_step(const float* __restrict__ v, const float* __restrict__ vo,
                       const float* __restrict__ z, const float* __restrict__ Faz,
                       const float* __restrict__ Fkz, const float* __restrict__ Fax,
                       const float* __restrict__ x, const float* __restrict__ w_out,
                       const float* __restrict__ yt, float* __restrict__ yo_out) {
    const int b = blockIdx.x;
    const int r = threadIdx.x;
    __shared__ float s_zn[NR];
    __shared__ float s_tmp[NO];

    const int ir = b * NR + r;
    const float zb = z[ir];
    const float vn = g_vpre[ir] + ALPHA * v[ir] * (1.f - zb);
    const float zn = (vn > 1.f) ? 1.f : 0.f;
    s_zn[r] = zn;
    const float h = fmaxf(0.f, 1.f - fabsf(vn - 1.f));
    g_Fazn[ir] = ALPHA * Faz[ir] + zb;
    g_Fkzn[ir] = KAPPA * Fkz[ir] + zn;
    __syncthreads();

    if (r < NO) {
        float a = KAPPA * vo[b * NO + r];
#pragma unroll 8
        for (int j = 0; j < NR; j++) a = fmaf(s_zn[j], w_out[r * NR + j], a);
        s_tmp[r] = a;
    }
    __syncthreads();

    if (r == 0) {
        float m = s_tmp[0];
#pragma unroll
        for (int o = 1; o < NO; o++) m = fmaxf(m, s_tmp[o]);
        float e[NO];
        float s = 0.f;
#pragma unroll
        for (int o = 0; o < NO; o++) { e[o] = expf(s_tmp[o] - m); s += e[o]; }
        const float inv = 1.f / s;
#pragma unroll
        for (int o = 0; o < NO; o++) {
            const float yo = e[o] * inv;
            yo_out[b * NO + o] = yo;
            const float er = yo - yt[b * NO + o];
            s_tmp[o] = er;
            g_err[b * NO + o] = er;
        }
    }
    __syncthreads();

    float L = 0.f;
#pragma unroll
    for (int o = 0; o < NO; o++) L = fmaf(s_tmp[o], w_out[o * NR + r], L);
    g_kL[ir] = KAPPA * L;
    g_Lh[ir] = L * h;

    for (int j = r; j < NI; j += NR)
        g_Faxn[b * NI + j] = ALPHA * Fax[b * NI + j] + x[b * NI + j];
}

// ---------------- rank-term GEMM: O[i,jj] = sum_b Lh[b,i] * C[b,jj] ----------------
// C = [Faxn (784) | Fazn (256)]; sources contiguous in i / jj -> loader indexes m with low bits
__global__ void k_outer(float* __restrict__ gwin, float* __restrict__ gwrec) {
    __shared__ float As[16][68];
    __shared__ float Bs[16][68];
    const int i0 = blockIdx.x * 64;
    const int j0 = blockIdx.y * 64;
    const int kb0 = blockIdx.z * 500;
    const int kb1 = kb0 + 500;
    const int tid = threadIdx.x;
    const int tr = tid >> 4, tc = tid & 15;

    float acc[4][4];
#pragma unroll
    for (int i = 0; i < 4; i++)
#pragma unroll
        for (int j = 0; j < 4; j++) acc[i][j] = 0.f;

    for (int kb = kb0; kb < kb1; kb += 16) {
#pragma unroll
        for (int l = 0; l < 4; l++) {
            int idx = tid + l * 256;
            int kk = idx >> 6;        // 0..15 over the 4 passes
            int m  = idx & 63;        // consecutive lanes -> consecutive m (coalesced)
            int k  = kb + kk;
            As[kk][m] = (k < kb1) ? g_Lh[k * NR + i0 + m] : 0.f;
            int jj = j0 + m;
            float bv = 0.f;
            if (k < kb1 && jj < 1040)
                bv = (jj < NI) ? g_Faxn[k * NI + jj] : g_Fazn[k * NR + (jj - NI)];
            Bs[kk][m] = bv;
        }
        __syncthreads();
#pragma unroll
        for (int kk = 0; kk < 16; kk++) {
            float ra[4], rb[4];
#pragma unroll
            for (int i = 0; i < 4; i++) ra[i] = As[kk][tr * 4 + i];
#pragma unroll
            for (int j = 0; j < 4; j++) rb[j] = Bs[kk][tc * 4 + j];
#pragma unroll
            for (int i = 0; i < 4; i++)
#pragma unroll
                for (int j = 0; j < 4; j++)
                    acc[i][j] = fmaf(ra[i], rb[j], acc[i][j]);
        }
        __syncthreads();
    }
#pragma unroll
    for (int i = 0; i < 4; i++) {
        int row = i0 + tr * 4 + i;
#pragma unroll
        for (int j = 0; j < 4; j++) {
            int jj = j0 + tc * 4 + j;
            if (jj < NI)            atomicAdd(&gwin[row * NI + jj], acc[i][j]);
            else if (jj < NI + NR)  atomicAdd(&gwrec[row * NR + (jj - NI)], acc[i][j]);
        }
    }
}

// ---------------- gw_out[o,r] = sum_b err[b,o] * Fkz_new[b,r] ----------------
__global__ void k_gwout(float* __restrict__ gwout) {
    const int chunk = blockIdx.x;        // 50 chunks of 20 batches
    const int r = threadIdx.x;
    const int b0 = chunk * 20;
    __shared__ float s_err[20 * NO];
    for (int t = r; t < 20 * NO; t += 256) s_err[t] = g_err[b0 * NO + t];
    __syncthreads();
    float acc[NO];
#pragma unroll
    for (int o = 0; o < NO; o++) acc[o] = 0.f;
    for (int bb = 0; bb < 20; bb++) {
        const float f = g_Fkzn[(b0 + bb) * NR + r];
#pragma unroll
        for (int o = 0; o < NO; o++) acc[o] = fmaf(s_err[bb * NO + o], f, acc[o]);
    }
#pragma unroll
    for (int o = 0; o < NO; o++) atomicAdd(&gwout[o * NR + r], acc[o]);
}

// ---------------- merged streaming kernel ----------------
// blocks [0, 1024):  gwin  — one (i, bs) per block, 196 active float4 lanes, 250 batches
// blocks [1024,1280): gwrec — 4 i-rows per block (64 float4 lanes each), 250 batches
#define NBLK_IN  1024
#define NBLK_REC 256
__global__ void __launch_bounds__(256)
k_stream(const float* __restrict__ Fke_in, const float* __restrict__ Fke_rec,
         float* __restrict__ gwin, float* __restrict__ gwrec) {
    __shared__ float s_kL[1000];
    const int t = threadIdx.x;

    if (blockIdx.x < NBLK_IN) {
        // ---- gwin path ----
        const int i  = blockIdx.x & 255;
        const int b0 = (blockIdx.x >> 8) * 250;
        for (int tt = t; tt < 250; tt += 256) s_kL[tt] = g_kL[(b0 + tt) * NR + i];
        __syncthreads();
        if (t >= 196) return;

        const float4* fke = (const float4*)(Fke_in + ((size_t)b0 * NR + i) * NI) + t;
        const size_t stride = (size_t)NR * NI / 4;
        float4 a0 = make_float4(0.f, 0.f, 0.f, 0.f);
        float4 a1 = make_float4(0.f, 0.f, 0.f, 0.f);
#pragma unroll 2
        for (int bb = 0; bb < 250; bb += 2) {
            float4 f0 = fke[(size_t)bb * stride];
            float4 f1 = fke[(size_t)(bb + 1) * stride];
            float c0 = s_kL[bb], c1 = s_kL[bb + 1];
            a0.x = fmaf(c0, f0.x, a0.x); a0.y = fmaf(c0, f0.y, a0.y);
            a0.z = fmaf(c0, f0.z, a0.z); a0.w = fmaf(c0, f0.w, a0.w);
            a1.x = fmaf(c1, f1.x, a1.x); a1.y = fmaf(c1, f1.y, a1.y);
            a1.z = fmaf(c1, f1.z, a1.z); a1.w = fmaf(c1, f1.w, a1.w);
        }
        float* dst = gwin + i * NI + t * 4;
        atomicAdd(dst + 0, a0.x + a1.x);
        atomicAdd(dst + 1, a0.y + a1.y);
        atomicAdd(dst + 2, a0.z + a1.z);
        atomicAdd(dst + 3, a0.w + a1.w);
    } else {
        // ---- gwrec path ----
        const int bi = blockIdx.x - NBLK_IN;   // 0..255
        const int i0 = (bi & 63) * 4;          // 4 i-rows per block
        const int b0 = (bi >> 6) * 250;
        const int li = t >> 6;                 // 0..3
        const int jv = t & 63;                 // float4 column
        for (int tt = t; tt < 1000; tt += 256) {
            int lr = tt / 250, bb = tt % 250;
            s_kL[lr * 250 + bb] = g_kL[(b0 + bb) * NR + i0 + lr];
        }
        __syncthreads();

        const int i = i0 + li;
        const float4* fke = (const float4*)(Fke_rec + ((size_t)b0 * NR + i) * NR) + jv;
        const size_t stride = (size_t)NR * NR / 4;
        const float* kl = s_kL + li * 250;
        float4 a0 = make_float4(0.f, 0.f, 0.f, 0.f);
        float4 a1 = make_float4(0.f, 0.f, 0.f, 0.f);
#pragma unroll 2
        for (int bb = 0; bb < 250; bb += 2) {
            float4 f0 = fke[(size_t)bb * stride];
            float4 f1 = fke[(size_t)(bb + 1) * stride];
            float c0 = kl[bb], c1 = kl[bb + 1];
            a0.x = fmaf(c0, f0.x, a0.x); a0.y = fmaf(c0, f0.y, a0.y);
            a0.z = fmaf(c0, f0.z, a0.z); a0.w = fmaf(c0, f0.w, a0.w);
            a1.x = fmaf(c1, f1.x, a1.x); a1.y = fmaf(c1, f1.y, a1.y);
            a1.z = fmaf(c1, f1.z, a1.z); a1.w = fmaf(c1, f1.w, a1.w);
        }
        float* dst = gwrec + i * NR + jv * 4;
        atomicAdd(dst + 0, a0.x + a1.x);
        atomicAdd(dst + 1, a0.y + a1.y);
        atomicAdd(dst + 2, a0.z + a1.z);
        atomicAdd(dst + 3, a0.w + a1.w);
    }
}

// ---------------- launch ----------------
extern "C" void kernel_launch(void* const* d_in, const int* in_sizes, int n_in,
                              void* d_out, int out_size) {
    const float* x       = (const float*)d_in[0];
    const float* yt      = (const float*)d_in[2];
    const float* w_in    = (const float*)d_in[3];
    const float* w_rec   = (const float*)d_in[4];
    const float* w_out   = (const float*)d_in[5];
    const float* v       = (const float*)d_in[6];
    const float* vo      = (const float*)d_in[7];
    const float* z       = (const float*)d_in[8];
    const float* Faz     = (const float*)d_in[9];
    const float* Fkz     = (const float*)d_in[10];
    const float* Fax     = (const float*)d_in[11];
    const float* Fke_rec = (const float*)d_in[12];
    const float* Fke_in  = (const float*)d_in[13];

    float* out     = (float*)d_out;
    float* yo_o    = out;
    float* gwin_o  = out + NB * NO;
    float* gwrec_o = gwin_o + NR * NI;
    float* gwout_o = gwrec_o + NR * NR;

    k_init<<<512, 256>>>(gwin_o, gwrec_o, gwout_o);
    k_gemm<<<dim3(16, 4, 2), 256>>>(x, z, w_in, w_rec);
    k_step<<<NB, NR>>>(v, vo, z, Faz, Fkz, Fax, x, w_out, yt, yo_o);
    k_outer<<<dim3(4, 17, 2), 256>>>(gwin_o, gwrec_o);
    k_gwout<<<50, 256>>>(gwout_o);
    k_stream<<<NBLK_IN + NBLK_REC, 256>>>(Fke_in, Fke_rec, gwin_o, gwrec_o);
}

// round 4
// speedup vs baseline: 1.6798x; 1.4082x over previous
#include <cuda_runtime.h>

// Problem dims
#define NB 1000
#define NI 784
#define NR 256
#define NO 10

#define ALPHA 0.8f
#define KAPPA 0.8f

#define NSPLIT 9           // k_gemm split-K count (chunks of 128 over K=1040)

// ---------------- scratch (__device__ globals; no allocation) ----------------
__device__ float g_vpre_p[NSPLIT * NB * NR];  // split-K partials (no atomics)
__device__ float g_kL  [NB * NR];
__device__ float g_Lh  [NB * NR];
__device__ float g_Fazn[NB * NR];
__device__ float g_Fkzn[NB * NR];
__device__ float g_Faxn[NB * NI];
__device__ float g_err [NB * NO];

// ---------------- init: zero atomic-target outputs ----------------
__global__ void k_init(float* __restrict__ gwin, float* __restrict__ gwrec,
                       float* __restrict__ gwout) {
    int idx = blockIdx.x * blockDim.x + threadIdx.x;
    int stride = gridDim.x * blockDim.x;
    for (int i = idx; i < NR * NI; i += stride) gwin[i] = 0.f;
    for (int i = idx; i < NR * NR; i += stride) gwrec[i] = 0.f;
    for (int i = idx; i < NO * NR; i += stride) gwout[i] = 0.f;
}

// ---------------- GEMM: vpre_p[s][b,r] = sum_{k in chunk s} A[b,k] * W[r,k] ----------------
// A = [x | z]  (K = 1040),  W = [w_in | w_rec(diag zeroed)]
// 9-way split-K (chunk 128), plain stores to per-split partials.
__global__ void k_gemm(const float* __restrict__ x, const float* __restrict__ z,
                       const float* __restrict__ w_in, const float* __restrict__ w_rec) {
    __shared__ float As[16][68];
    __shared__ float Ws[16][68];
    const int row0 = blockIdx.x * 64;
    const int col0 = blockIdx.y * 64;
    const int split = blockIdx.z;
    const int tid = threadIdx.x;
    const int tr = tid >> 4, tc = tid & 15;

    const int k_begin = split * 128;
    const int k_end   = (k_begin + 128 < 1040) ? (k_begin + 128) : 1040;

    float acc[4][4];
#pragma unroll
    for (int i = 0; i < 4; i++)
#pragma unroll
        for (int j = 0; j < 4; j++) acc[i][j] = 0.f;

    for (int kb = k_begin; kb < k_end; kb += 16) {
#pragma unroll
        for (int l = 0; l < 4; l++) {
            int idx = tid + l * 256;
            int kk = idx & 15;
            int m  = idx >> 4;
            int k  = kb + kk;
            int b = row0 + m;
            float av = 0.f;
            if (b < NB) av = (k < NI) ? x[b * NI + k] : z[b * NR + (k - NI)];
            As[kk][m] = av;
            int r = col0 + m;
            float wv;
            if (k < NI) {
                wv = w_in[r * NI + k];
            } else {
                int kr = k - NI;
                wv = (kr == r) ? 0.f : w_rec[r * NR + kr];
            }
            Ws[kk][m] = wv;
        }
        __syncthreads();
#pragma unroll
        for (int kk = 0; kk < 16; kk++) {
            float ra[4], rw[4];
#pragma unroll
            for (int i = 0; i < 4; i++) ra[i] = As[kk][tr * 4 + i];
#pragma unroll
            for (int j = 0; j < 4; j++) rw[j] = Ws[kk][tc * 4 + j];
#pragma unroll
            for (int i = 0; i < 4; i++)
#pragma unroll
                for (int j = 0; j < 4; j++)
                    acc[i][j] = fmaf(ra[i], rw[j], acc[i][j]);
        }
        __syncthreads();
    }
    float* dst = g_vpre_p + (size_t)split * NB * NR;
#pragma unroll
    for (int i = 0; i < 4; i++) {
        int b = row0 + tr * 4 + i;
        if (b < NB) {
#pragma unroll
            for (int j = 0; j < 4; j++)
                dst[b * NR + col0 + tc * 4 + j] = acc[i][j];
        }
    }
}

// ---------------- per-batch fused step ----------------
__global__ void k_step(const float* __restrict__ v, const float* __restrict__ vo,
                       const float* __restrict__ z, const float* __restrict__ Faz,
                       const float* __restrict__ Fkz, const float* __restrict__ Fax,
                       const float* __restrict__ x, const float* __restrict__ w_out,
                       const float* __restrict__ yt, float* __restrict__ yo_out) {
    const int b = blockIdx.x;
    const int r = threadIdx.x;
    __shared__ float s_zn[NR];
    __shared__ float s_tmp[NO];

    const int ir = b * NR + r;
    float vpre = 0.f;
#pragma unroll
    for (int s = 0; s < NSPLIT; s++) vpre += g_vpre_p[(size_t)s * NB * NR + ir];

    const float zb = z[ir];
    const float vn = vpre + ALPHA * v[ir] * (1.f - zb);
    const float zn = (vn > 1.f) ? 1.f : 0.f;
    s_zn[r] = zn;
    const float h = fmaxf(0.f, 1.f - fabsf(vn - 1.f));
    g_Fazn[ir] = ALPHA * Faz[ir] + zb;
    g_Fkzn[ir] = KAPPA * Fkz[ir] + zn;
    __syncthreads();

    if (r < NO) {
        float a = KAPPA * vo[b * NO + r];
#pragma unroll 8
        for (int j = 0; j < NR; j++) a = fmaf(s_zn[j], w_out[r * NR + j], a);
        s_tmp[r] = a;
    }
    __syncthreads();

    if (r == 0) {
        float m = s_tmp[0];
#pragma unroll
        for (int o = 1; o < NO; o++) m = fmaxf(m, s_tmp[o]);
        float e[NO];
        float s = 0.f;
#pragma unroll
        for (int o = 0; o < NO; o++) { e[o] = expf(s_tmp[o] - m); s += e[o]; }
        const float inv = 1.f / s;
#pragma unroll
        for (int o = 0; o < NO; o++) {
            const float yo = e[o] * inv;
            yo_out[b * NO + o] = yo;
            const float er = yo - yt[b * NO + o];
            s_tmp[o] = er;
            g_err[b * NO + o] = er;
        }
    }
    __syncthreads();

    float L = 0.f;
#pragma unroll
    for (int o = 0; o < NO; o++) L = fmaf(s_tmp[o], w_out[o * NR + r], L);
    g_kL[ir] = KAPPA * L;
    g_Lh[ir] = L * h;

    for (int j = r; j < NI; j += NR)
        g_Faxn[b * NI + j] = ALPHA * Fax[b * NI + j] + x[b * NI + j];
}

// ================= MEGA KERNEL =================
// Roles (Bresenham-interleaved, period 16 = 5 special + 11 stream):
//   special: 544 outer-GEMM blocks (split-b 8) + 50 gwout blocks  (594)
//   stream : 1024 gwin blocks + 256 gwrec blocks                   (1280)
// periods = 120 -> grid = 1920 (few no-op slack blocks)
#define N_OUTER 544
#define N_SPECIAL 594
#define N_GWIN 1024
#define N_STREAM 1280
#define MEGA_GRID 1920

__device__ __forceinline__ void do_outer(int oid, float* smem,
                                         float* __restrict__ gwin,
                                         float* __restrict__ gwrec) {
    // O[i,jj] = sum_b Lh[b,i] * C[b,jj],  C = [Faxn(784) | Fazn(256)]
    float (*As)[68] = (float(*)[68])smem;           // [16][68]
    float (*Bs)[68] = (float(*)[68])(smem + 1088);  // [16][68]
    const int split = oid / 68;            // 0..7, b-chunks of 125
    const int rem   = oid % 68;
    const int i0 = (rem & 3) * 64;
    const int j0 = (rem >> 2) * 64;
    const int kb0 = split * 125;
    const int kb1 = kb0 + 125;
    const int tid = threadIdx.x;
    const int tr = tid >> 4, tc = tid & 15;

    float acc[4][4];
#pragma unroll
    for (int i = 0; i < 4; i++)
#pragma unroll
        for (int j = 0; j < 4; j++) acc[i][j] = 0.f;

    for (int kb = kb0; kb < kb1; kb += 16) {
#pragma unroll
        for (int l = 0; l < 4; l++) {
            int idx = tid + l * 256;
            int kk = idx >> 6;
            int m  = idx & 63;       // consecutive lanes -> consecutive i/jj (coalesced)
            int k  = kb + kk;
            As[kk][m] = (k < kb1) ? g_Lh[k * NR + i0 + m] : 0.f;
            int jj = j0 + m;
            float bv = 0.f;
            if (k < kb1 && jj < 1040)
                bv = (jj < NI) ? g_Faxn[k * NI + jj] : g_Fazn[k * NR + (jj - NI)];
            Bs[kk][m] = bv;
        }
        __syncthreads();
#pragma unroll
        for (int kk = 0; kk < 16; kk++) {
            float ra[4], rb[4];
#pragma unroll
            for (int i = 0; i < 4; i++) ra[i] = As[kk][tr * 4 + i];
#pragma unroll
            for (int j = 0; j < 4; j++) rb[j] = Bs[kk][tc * 4 + j];
#pragma unroll
            for (int i = 0; i < 4; i++)
#pragma unroll
                for (int j = 0; j < 4; j++)
                    acc[i][j] = fmaf(ra[i], rb[j], acc[i][j]);
        }
        __syncthreads();
    }
#pragma unroll
    for (int i = 0; i < 4; i++) {
        int row = i0 + tr * 4 + i;
#pragma unroll
        for (int j = 0; j < 4; j++) {
            int jj = j0 + tc * 4 + j;
            if (jj < NI)            atomicAdd(&gwin[row * NI + jj], acc[i][j]);
            else if (jj < NI + NR)  atomicAdd(&gwrec[row * NR + (jj - NI)], acc[i][j]);
        }
    }
}

__device__ __forceinline__ void do_gwout(int cid, float* smem, float* __restrict__ gwout) {
    // gw_out[o,r] = sum_b err[b,o] * Fkz_new[b,r]  (50 chunks of 20 batches)
    float* s_err = smem;
    const int r = threadIdx.x;
    const int b0 = cid * 20;
    for (int t = r; t < 20 * NO; t += 256) s_err[t] = g_err[b0 * NO + t];
    __syncthreads();
    float acc[NO];
#pragma unroll
    for (int o = 0; o < NO; o++) acc[o] = 0.f;
    for (int bb = 0; bb < 20; bb++) {
        const float f = g_Fkzn[(b0 + bb) * NR + r];
#pragma unroll
        for (int o = 0; o < NO; o++) acc[o] = fmaf(s_err[bb * NO + o], f, acc[o]);
    }
#pragma unroll
    for (int o = 0; o < NO; o++) atomicAdd(&gwout[o * NR + r], acc[o]);
}

__device__ __forceinline__ void do_gwin(int sid, float* smem,
                                        const float* __restrict__ Fke_in,
                                        float* __restrict__ gwin) {
    float* s_kL = smem;
    const int t = threadIdx.x;
    const int i  = sid & 255;
    const int b0 = (sid >> 8) * 250;
    for (int tt = t; tt < 250; tt += 256) s_kL[tt] = g_kL[(b0 + tt) * NR + i];
    __syncthreads();
    if (t >= 196) return;

    const float4* fke = (const float4*)(Fke_in + ((size_t)b0 * NR + i) * NI) + t;
    const size_t stride = (size_t)NR * NI / 4;
    float4 a0 = make_float4(0.f, 0.f, 0.f, 0.f);
    float4 a1 = make_float4(0.f, 0.f, 0.f, 0.f);
#pragma unroll 2
    for (int bb = 0; bb < 250; bb += 2) {
        float4 f0 = fke[(size_t)bb * stride];
        float4 f1 = fke[(size_t)(bb + 1) * stride];
        float c0 = s_kL[bb], c1 = s_kL[bb + 1];
        a0.x = fmaf(c0, f0.x, a0.x); a0.y = fmaf(c0, f0.y, a0.y);
        a0.z = fmaf(c0, f0.z, a0.z); a0.w = fmaf(c0, f0.w, a0.w);
        a1.x = fmaf(c1, f1.x, a1.x); a1.y = fmaf(c1, f1.y, a1.y);
        a1.z = fmaf(c1, f1.z, a1.z); a1.w = fmaf(c1, f1.w, a1.w);
    }
    float* dst = gwin + i * NI + t * 4;
    atomicAdd(dst + 0, a0.x + a1.x);
    atomicAdd(dst + 1, a0.y + a1.y);
    atomicAdd(dst + 2, a0.z + a1.z);
    atomicAdd(dst + 3, a0.w + a1.w);
}

__device__ __forceinline__ void do_gwrec(int sid, float* smem,
                                         const float* __restrict__ Fke_rec,
                                         float* __restrict__ gwrec) {
    float* s_kL = smem;   // 1000 floats (4 rows x 250)
    const int t = threadIdx.x;
    const int i0 = (sid & 63) * 4;
    const int b0 = (sid >> 6) * 250;
    const int li = t >> 6;
    const int jv = t & 63;
    for (int tt = t; tt < 1000; tt += 256) {
        int lr = tt / 250, bb = tt % 250;
        s_kL[lr * 250 + bb] = g_kL[(b0 + bb) * NR + i0 + lr];
    }
    __syncthreads();

    const int i = i0 + li;
    const float4* fke = (const float4*)(Fke_rec + ((size_t)b0 * NR + i) * NR) + jv;
    const size_t stride = (size_t)NR * NR / 4;
    const float* kl = s_kL + li * 250;
    float4 a0 = make_float4(0.f, 0.f, 0.f, 0.f);
    float4 a1 = make_float4(0.f, 0.f, 0.f, 0.f);
#pragma unroll 2
    for (int bb = 0; bb < 250; bb += 2) {
        float4 f0 = fke[(size_t)bb * stride];
        float4 f1 = fke[(size_t)(bb + 1) * stride];
        float c0 = kl[bb], c1 = kl[bb + 1];
        a0.x = fmaf(c0, f0.x, a0.x); a0.y = fmaf(c0, f0.y, a0.y);
        a0.z = fmaf(c0, f0.z, a0.z); a0.w = fmaf(c0, f0.w, a0.w);
        a1.x = fmaf(c1, f1.x, a1.x); a1.y = fmaf(c1, f1.y, a1.y);
        a1.z = fmaf(c1, f1.z, a1.z); a1.w = fmaf(c1, f1.w, a1.w);
    }
    float* dst = gwrec + i * NR + jv * 4;
    atomicAdd(dst + 0, a0.x + a1.x);
    atomicAdd(dst + 1, a0.y + a1.y);
    atomicAdd(dst + 2, a0.z + a1.z);
    atomicAdd(dst + 3, a0.w + a1.w);
}

__global__ void __launch_bounds__(256)
k_mega(const float* __restrict__ Fke_in, const float* __restrict__ Fke_rec,
       float* __restrict__ gwin, float* __restrict__ gwrec, float* __restrict__ gwout) {
    __shared__ float smem[2176];   // union: outer 2x16x68, streams <=1000, gwout 200
    const int p = blockIdx.x >> 4;
    const int l = blockIdx.x & 15;
    if (l < 5) {
        int sid = p * 5 + l;
        if (sid >= N_SPECIAL) return;
        if (sid < N_OUTER) do_outer(sid, smem, gwin, gwrec);
        else               do_gwout(sid - N_OUTER, smem, gwout);
    } else {
        int sid = p * 11 + (l - 5);
        if (sid >= N_STREAM) return;
        if (sid < N_GWIN) do_gwin(sid, smem, Fke_in, gwin);
        else              do_gwrec(sid - N_GWIN, smem, Fke_rec, gwrec);
    }
}

// ---------------- launch ----------------
extern "C" void kernel_launch(void* const* d_in, const int* in_sizes, int n_in,
                              void* d_out, int out_size) {
    const float* x       = (const float*)d_in[0];
    const float* yt      = (const float*)d_in[2];
    const float* w_in    = (const float*)d_in[3];
    const float* w_rec   = (const float*)d_in[4];
    const float* w_out   = (const float*)d_in[5];
    const float* v       = (const float*)d_in[6];
    const float* vo      = (const float*)d_in[7];
    const float* z       = (const float*)d_in[8];
    const float* Faz     = (const float*)d_in[9];
    const float* Fkz     = (const float*)d_in[10];
    const float* Fax     = (const float*)d_in[11];
    const float* Fke_rec = (const float*)d_in[12];
    const float* Fke_in  = (const float*)d_in[13];

    float* out     = (float*)d_out;
    float* yo_o    = out;
    float* gwin_o  = out + NB * NO;
    float* gwrec_o = gwin_o + NR * NI;
    float* gwout_o = gwrec_o + NR * NR;

    k_init<<<512, 256>>>(gwin_o, gwrec_o, gwout_o);
    k_gemm<<<dim3(16, 4, NSPLIT), 256>>>(x, z, w_in, w_rec);
    k_step<<<NB, NR>>>(v, vo, z, Faz, Fkz, Fax, x, w_out, yt, yo_o);
    k_mega<<<MEGA_GRID, 256>>>(Fke_in, Fke_rec, gwin_o, gwrec_o, gwout_o);
}

// round 5
// speedup vs baseline: 1.8019x; 1.0727x over previous
#include <cuda_runtime.h>

// Problem dims
#define NB 1000
#define NI 784
#define NR 256
#define NO 10

#define ALPHA 0.8f
#define KAPPA 0.8f

#define NSPLIT 9           // gemm split-K count (chunks of 128 over K=1040)

// ---------------- scratch (__device__ globals; no allocation) ----------------
__device__ float g_vpre_p[NSPLIT * NB * NR];  // split-K partials (no atomics)
__device__ float g_kL  [NB * NR];
__device__ float g_Lh  [NB * NR];
__device__ float g_Fazn[NB * NR];
__device__ float g_Fkzn[NB * NR];
__device__ float g_Faxn[NB * NI];
__device__ float g_err [NB * NO];

// ================= PREP KERNEL: gemm tiles + output zeroing in one launch =================
// blocks [0,576): vpre split-K GEMM tiles;  blocks [576,640): zero gwin/gwrec/gwout
#define N_GEMM 576
#define PREP_GRID 640

__global__ void __launch_bounds__(256)
k_prep(const float* __restrict__ x, const float* __restrict__ z,
       const float* __restrict__ w_in, const float* __restrict__ w_rec,
       float* __restrict__ gwin, float* __restrict__ gwrec, float* __restrict__ gwout) {
    if (blockIdx.x >= N_GEMM) {
        // ---- zero role ----
        int idx = (blockIdx.x - N_GEMM) * 256 + threadIdx.x;
        int stride = (PREP_GRID - N_GEMM) * 256;
        for (int i = idx; i < NR * NI; i += stride) gwin[i] = 0.f;
        for (int i = idx; i < NR * NR; i += stride) gwrec[i] = 0.f;
        for (int i = idx; i < NO * NR; i += stride) gwout[i] = 0.f;
        return;
    }
    // ---- GEMM role: vpre_p[s][b,r] = sum_{k in chunk s} A[b,k] * W[r,k] ----
    // A = [x | z] (K=1040), W = [w_in | w_rec(diag zeroed)]
    __shared__ float As[16][68];
    __shared__ float Ws[16][68];
    const int bi = blockIdx.x;
    const int split = bi >> 6;           // 0..8
    const int rem   = bi & 63;
    const int row0 = (rem & 15) * 64;    // batch tile
    const int col0 = (rem >> 4) * 64;    // rec-unit tile
    const int tid = threadIdx.x;
    const int tr = tid >> 4, tc = tid & 15;

    const int k_begin = split * 128;
    const int k_end   = (k_begin + 128 < 1040) ? (k_begin + 128) : 1040;

    float acc[4][4];
#pragma unroll
    for (int i = 0; i < 4; i++)
#pragma unroll
        for (int j = 0; j < 4; j++) acc[i][j] = 0.f;

    for (int kb = k_begin; kb < k_end; kb += 16) {
#pragma unroll
        for (int l = 0; l < 4; l++) {
            int idx = tid + l * 256;
            int kk = idx & 15;
            int m  = idx >> 4;
            int k  = kb + kk;
            int b = row0 + m;
            float av = 0.f;
            if (b < NB) av = (k < NI) ? x[b * NI + k] : z[b * NR + (k - NI)];
            As[kk][m] = av;
            int r = col0 + m;
            float wv;
            if (k < NI) {
                wv = w_in[r * NI + k];
            } else {
                int kr = k - NI;
                wv = (kr == r) ? 0.f : w_rec[r * NR + kr];
            }
            Ws[kk][m] = wv;
        }
        __syncthreads();
#pragma unroll
        for (int kk = 0; kk < 16; kk++) {
            float ra[4], rw[4];
#pragma unroll
            for (int i = 0; i < 4; i++) ra[i] = As[kk][tr * 4 + i];
#pragma unroll
            for (int j = 0; j < 4; j++) rw[j] = Ws[kk][tc * 4 + j];
#pragma unroll
            for (int i = 0; i < 4; i++)
#pragma unroll
                for (int j = 0; j < 4; j++)
                    acc[i][j] = fmaf(ra[i], rw[j], acc[i][j]);
        }
        __syncthreads();
    }
    float* dst = g_vpre_p + (size_t)split * NB * NR;
#pragma unroll
    for (int i = 0; i < 4; i++) {
        int b = row0 + tr * 4 + i;
        if (b < NB) {
            float4 vv = make_float4(acc[i][0], acc[i][1], acc[i][2], acc[i][3]);
            *(float4*)(dst + b * NR + col0 + tc * 4) = vv;
        }
    }
}

// ---------------- per-batch fused step ----------------
__global__ void __launch_bounds__(256)
k_step(const float* __restrict__ v, const float* __restrict__ vo,
       const float* __restrict__ z, const float* __restrict__ Faz,
       const float* __restrict__ Fkz, const float* __restrict__ Fax,
       const float* __restrict__ x, const float* __restrict__ w_out,
       const float* __restrict__ yt, float* __restrict__ yo_out) {
    const int b = blockIdx.x;
    const int r = threadIdx.x;
    __shared__ float s_zn[NR];
    __shared__ float s_tmp[NO];

    const int ir = b * NR + r;
    float vpre = 0.f;
#pragma unroll
    for (int s = 0; s < NSPLIT; s++) vpre += g_vpre_p[(size_t)s * NB * NR + ir];

    const float zb = z[ir];
    const float vn = vpre + ALPHA * v[ir] * (1.f - zb);
    const float zn = (vn > 1.f) ? 1.f : 0.f;
    s_zn[r] = zn;
    const float h = fmaxf(0.f, 1.f - fabsf(vn - 1.f));
    g_Fazn[ir] = ALPHA * Faz[ir] + zb;
    g_Fkzn[ir] = KAPPA * Fkz[ir] + zn;

    // Faxn: 784 = 196 float4 per batch, one per thread (r < 196)
    if (r < 196) {
        const float4 fx = ((const float4*)(Fax + b * NI))[r];
        const float4 xx = ((const float4*)(x + b * NI))[r];
        float4 o;
        o.x = fmaf(ALPHA, fx.x, xx.x);
        o.y = fmaf(ALPHA, fx.y, xx.y);
        o.z = fmaf(ALPHA, fx.z, xx.z);
        o.w = fmaf(ALPHA, fx.w, xx.w);
        ((float4*)(g_Faxn + b * NI))[r] = o;
    }
    __syncthreads();

    if (r < NO) {
        float a = KAPPA * vo[b * NO + r];
#pragma unroll 8
        for (int j = 0; j < NR; j++) a = fmaf(s_zn[j], w_out[r * NR + j], a);
        s_tmp[r] = a;
    }
    __syncthreads();

    if (r == 0) {
        float m = s_tmp[0];
#pragma unroll
        for (int o = 1; o < NO; o++) m = fmaxf(m, s_tmp[o]);
        float e[NO];
        float s = 0.f;
#pragma unroll
        for (int o = 0; o < NO; o++) { e[o] = expf(s_tmp[o] - m); s += e[o]; }
        const float inv = 1.f / s;
#pragma unroll
        for (int o = 0; o < NO; o++) {
            const float yo = e[o] * inv;
            yo_out[b * NO + o] = yo;
            const float er = yo - yt[b * NO + o];
            s_tmp[o] = er;
            g_err[b * NO + o] = er;
        }
    }
    __syncthreads();

    float L = 0.f;
#pragma unroll
    for (int o = 0; o < NO; o++) L = fmaf(s_tmp[o], w_out[o * NR + r], L);
    g_kL[ir] = KAPPA * L;
    g_Lh[ir] = L * h;
}

// ================= MEGA KERNEL =================
// Roles (Bresenham-interleaved, period 16 = 5 special + 11 stream):
//   special: 544 outer-GEMM blocks (split-b 8) + 50 gwout blocks  (594)
//   stream : 1024 gwin blocks + 256 gwrec blocks                   (1280)
#define N_OUTER 544
#define N_SPECIAL 594
#define N_GWIN 1024
#define N_STREAM 1280
#define MEGA_GRID 1920

__device__ __forceinline__ void do_outer(int oid, float* smem,
                                         float* __restrict__ gwin,
                                         float* __restrict__ gwrec) {
    // O[i,jj] = sum_b Lh[b,i] * C[b,jj],  C = [Faxn(784) | Fazn(256)]
    float (*As)[68] = (float(*)[68])smem;
    float (*Bs)[68] = (float(*)[68])(smem + 1088);
    const int split = oid / 68;            // 0..7, b-chunks of 125
    const int rem   = oid % 68;
    const int i0 = (rem & 3) * 64;
    const int j0 = (rem >> 2) * 64;
    const int kb0 = split * 125;
    const int kb1 = kb0 + 125;
    const int tid = threadIdx.x;
    const int tr = tid >> 4, tc = tid & 15;

    float acc[4][4];
#pragma unroll
    for (int i = 0; i < 4; i++)
#pragma unroll
        for (int j = 0; j < 4; j++) acc[i][j] = 0.f;

    for (int kb = kb0; kb < kb1; kb += 16) {
#pragma unroll
        for (int l = 0; l < 4; l++) {
            int idx = tid + l * 256;
            int kk = idx >> 6;
            int m  = idx & 63;
            int k  = kb + kk;
            As[kk][m] = (k < kb1) ? g_Lh[k * NR + i0 + m] : 0.f;
            int jj = j0 + m;
            float bv = 0.f;
            if (k < kb1 && jj < 1040)
                bv = (jj < NI) ? g_Faxn[k * NI + jj] : g_Fazn[k * NR + (jj - NI)];
            Bs[kk][m] = bv;
        }
        __syncthreads();
#pragma unroll
        for (int kk = 0; kk < 16; kk++) {
            float ra[4], rb[4];
#pragma unroll
            for (int i = 0; i < 4; i++) ra[i] = As[kk][tr * 4 + i];
#pragma unroll
            for (int j = 0; j < 4; j++) rb[j] = Bs[kk][tc * 4 + j];
#pragma unroll
            for (int i = 0; i < 4; i++)
#pragma unroll
                for (int j = 0; j < 4; j++)
                    acc[i][j] = fmaf(ra[i], rb[j], acc[i][j]);
        }
        __syncthreads();
    }
#pragma unroll
    for (int i = 0; i < 4; i++) {
        int row = i0 + tr * 4 + i;
#pragma unroll
        for (int j = 0; j < 4; j++) {
            int jj = j0 + tc * 4 + j;
            if (jj < NI)            atomicAdd(&gwin[row * NI + jj], acc[i][j]);
            else if (jj < NI + NR)  atomicAdd(&gwrec[row * NR + (jj - NI)], acc[i][j]);
        }
    }
}

__device__ __forceinline__ void do_gwout(int cid, float* smem, float* __restrict__ gwout) {
    float* s_err = smem;
    const int r = threadIdx.x;
    const int b0 = cid * 20;
    for (int t = r; t < 20 * NO; t += 256) s_err[t] = g_err[b0 * NO + t];
    __syncthreads();
    float acc[NO];
#pragma unroll
    for (int o = 0; o < NO; o++) acc[o] = 0.f;
    for (int bb = 0; bb < 20; bb++) {
        const float f = g_Fkzn[(b0 + bb) * NR + r];
#pragma unroll
        for (int o = 0; o < NO; o++) acc[o] = fmaf(s_err[bb * NO + o], f, acc[o]);
    }
#pragma unroll
    for (int o = 0; o < NO; o++) atomicAdd(&gwout[o * NR + r], acc[o]);
}

#define FMA4(A, C, F) \
    A.x = fmaf(C, F.x, A.x); A.y = fmaf(C, F.y, A.y); \
    A.z = fmaf(C, F.z, A.z); A.w = fmaf(C, F.w, A.w);

__device__ __forceinline__ void do_gwin(int sid, float* smem,
                                        const float* __restrict__ Fke_in,
                                        float* __restrict__ gwin) {
    float* s_kL = smem;
    const int t = threadIdx.x;
    const int i  = sid & 255;
    const int b0 = (sid >> 8) * 250;
    for (int tt = t; tt < 250; tt += 256) s_kL[tt] = g_kL[(b0 + tt) * NR + i];
    __syncthreads();
    if (t >= 196) return;

    const float4* fke = (const float4*)(Fke_in + ((size_t)b0 * NR + i) * NI) + t;
    const size_t stride = (size_t)NR * NI / 4;
    float4 a0 = make_float4(0.f, 0.f, 0.f, 0.f);
    float4 a1 = make_float4(0.f, 0.f, 0.f, 0.f);
    float4 a2 = make_float4(0.f, 0.f, 0.f, 0.f);
    float4 a3 = make_float4(0.f, 0.f, 0.f, 0.f);
#pragma unroll 1
    for (int bb = 0; bb < 248; bb += 4) {
        float4 f0 = fke[(size_t)(bb + 0) * stride];
        float4 f1 = fke[(size_t)(bb + 1) * stride];
        float4 f2 = fke[(size_t)(bb + 2) * stride];
        float4 f3 = fke[(size_t)(bb + 3) * stride];
        float c0 = s_kL[bb], c1 = s_kL[bb + 1], c2 = s_kL[bb + 2], c3 = s_kL[bb + 3];
        FMA4(a0, c0, f0) FMA4(a1, c1, f1) FMA4(a2, c2, f2) FMA4(a3, c3, f3)
    }
    {
        float4 f0 = fke[(size_t)248 * stride];
        float4 f1 = fke[(size_t)249 * stride];
        float c0 = s_kL[248], c1 = s_kL[249];
        FMA4(a0, c0, f0) FMA4(a1, c1, f1)
    }
    float* dst = gwin + i * NI + t * 4;
    atomicAdd(dst + 0, (a0.x + a1.x) + (a2.x + a3.x));
    atomicAdd(dst + 1, (a0.y + a1.y) + (a2.y + a3.y));
    atomicAdd(dst + 2, (a0.z + a1.z) + (a2.z + a3.z));
    atomicAdd(dst + 3, (a0.w + a1.w) + (a2.w + a3.w));
}

__device__ __forceinline__ void do_gwrec(int sid, float* smem,
                                         const float* __restrict__ Fke_rec,
                                         float* __restrict__ gwrec) {
    float* s_kL = smem;   // 1000 floats (4 rows x 250)
    const int t = threadIdx.x;
    const int i0 = (sid & 63) * 4;
    const int b0 = (sid >> 6) * 250;
    const int li = t >> 6;
    const int jv = t & 63;
    for (int tt = t; tt < 1000; tt += 256) {
        int lr = tt / 250, bb = tt % 250;
        s_kL[lr * 250 + bb] = g_kL[(b0 + bb) * NR + i0 + lr];
    }
    __syncthreads();

    const int i = i0 + li;
    const float4* fke = (const float4*)(Fke_rec + ((size_t)b0 * NR + i) * NR) + jv;
    const size_t stride = (size_t)NR * NR / 4;
    const float* kl = s_kL + li * 250;
    float4 a0 = make_float4(0.f, 0.f, 0.f, 0.f);
    float4 a1 = make_float4(0.f, 0.f, 0.f, 0.f);
    float4 a2 = make_float4(0.f, 0.f, 0.f, 0.f);
    float4 a3 = make_float4(0.f, 0.f, 0.f, 0.f);
#pragma unroll 1
    for (int bb = 0; bb < 248; bb += 4) {
        float4 f0 = fke[(size_t)(bb + 0) * stride];
        float4 f1 = fke[(size_t)(bb + 1) * stride];
        float4 f2 = fke[(size_t)(bb + 2) * stride];
        float4 f3 = fke[(size_t)(bb + 3) * stride];
        float c0 = kl[bb], c1 = kl[bb + 1], c2 = kl[bb + 2], c3 = kl[bb + 3];
        FMA4(a0, c0, f0) FMA4(a1, c1, f1) FMA4(a2, c2, f2) FMA4(a3, c3, f3)
    }
    {
        float4 f0 = fke[(size_t)248 * stride];
        float4 f1 = fke[(size_t)249 * stride];
        float c0 = kl[248], c1 = kl[249];
        FMA4(a0, c0, f0) FMA4(a1, c1, f1)
    }
    float* dst = gwrec + i * NR + jv * 4;
    atomicAdd(dst + 0, (a0.x + a1.x) + (a2.x + a3.x));
    atomicAdd(dst + 1, (a0.y + a1.y) + (a2.y + a3.y));
    atomicAdd(dst + 2, (a0.z + a1.z) + (a2.z + a3.z));
    atomicAdd(dst + 3, (a0.w + a1.w) + (a2.w + a3.w));
}

__global__ void __launch_bounds__(256)
k_mega(const float* __restrict__ Fke_in, const float* __restrict__ Fke_rec,
       float* __restrict__ gwin, float* __restrict__ gwrec, float* __restrict__ gwout) {
    __shared__ float smem[2176];
    const int p = blockIdx.x >> 4;
    const int l = blockIdx.x & 15;
    if (l < 5) {
        int sid = p * 5 + l;
        if (sid >= N_SPECIAL) return;
        if (sid < N_OUTER) do_outer(sid, smem, gwin, gwrec);
        else               do_gwout(sid - N_OUTER, smem, gwout);
    } else {
        int sid = p * 11 + (l - 5);
        if (sid >= N_STREAM) return;
        if (sid < N_GWIN) do_gwin(sid, smem, Fke_in, gwin);
        else              do_gwrec(sid - N_GWIN, smem, Fke_rec, gwrec);
    }
}

// ---------------- launch ----------------
extern "C" void kernel_launch(void* const* d_in, const int* in_sizes, int n_in,
                              void* d_out, int out_size) {
    const float* x       = (const float*)d_in[0];
    const float* yt      = (const float*)d_in[2];
    const float* w_in    = (const float*)d_in[3];
    const float* w_rec   = (const float*)d_in[4];
    const float* w_out   = (const float*)d_in[5];
    const float* v       = (const float*)d_in[6];
    const float* vo      = (const float*)d_in[7];
    const float* z       = (const float*)d_in[8];
    const float* Faz     = (const float*)d_in[9];
    const float* Fkz     = (const float*)d_in[10];
    const float* Fax     = (const float*)d_in[11];
    const float* Fke_rec = (const float*)d_in[12];
    const float* Fke_in  = (const float*)d_in[13];

    float* out     = (float*)d_out;
    float* yo_o    = out;
    float* gwin_o  = out + NB * NO;
    float* gwrec_o = gwin_o + NR * NI;
    float* gwout_o = gwrec_o + NR * NR;

    k_prep<<<PREP_GRID, 256>>>(x, z, w_in, w_rec, gwin_o, gwrec_o, gwout_o);
    k_step<<<NB, NR>>>(v, vo, z, Faz, Fkz, Fax, x, w_out, yt, yo_o);
    k_mega<<<MEGA_GRID, 256>>>(Fke_in, Fke_rec, gwin_o, gwrec_o, gwout_o);
}

// round 6
// speedup vs baseline: 1.9253x; 1.0685x over previous
#include <cuda_runtime.h>

// Problem dims
#define NB 1000
#define NI 784
#define NR 256
#define NO 10

#define ALPHA 0.8f
#define KAPPA 0.8f

#define NSPLIT 9           // gemm split-K count (chunks of 128 over K=1040)

// ---------------- scratch (__device__ globals; no allocation) ----------------
__device__ float g_vpre_p[NSPLIT * NB * NR];  // split-K partials (no atomics)
__device__ float g_kL  [NB * NR];
__device__ float g_Lh  [NB * NR];
__device__ float g_Fazn[NB * NR];
__device__ float g_Fkzn[NB * NR];
__device__ float g_Faxn[NB * NI];
__device__ float g_err [NB * NO];

// ================= PREP KERNEL: gemm tiles + output zeroing in one launch =================
// blocks [0,576): vpre split-K GEMM tiles;  blocks [576,640): zero gwin/gwrec/gwout
#define N_GEMM 576
#define PREP_GRID 640

__global__ void __launch_bounds__(256)
k_prep(const float* __restrict__ x, const float* __restrict__ z,
       const float* __restrict__ w_in, const float* __restrict__ w_rec,
       float* __restrict__ gwin, float* __restrict__ gwrec, float* __restrict__ gwout) {
    if (blockIdx.x >= N_GEMM) {
        int idx = (blockIdx.x - N_GEMM) * 256 + threadIdx.x;
        int stride = (PREP_GRID - N_GEMM) * 256;
        for (int i = idx; i < NR * NI; i += stride) gwin[i] = 0.f;
        for (int i = idx; i < NR * NR; i += stride) gwrec[i] = 0.f;
        for (int i = idx; i < NO * NR; i += stride) gwout[i] = 0.f;
        return;
    }
    // ---- GEMM role: vpre_p[s][b,r] = sum_{k in chunk s} A[b,k] * W[r,k] ----
    __shared__ __align__(16) float As[16][68];
    __shared__ __align__(16) float Ws[16][68];
    const int bi = blockIdx.x;
    const int split = bi >> 6;           // 0..8
    const int rem   = bi & 63;
    const int row0 = (rem & 15) * 64;    // batch tile
    const int col0 = (rem >> 4) * 64;    // rec-unit tile
    const int tid = threadIdx.x;
    const int tr = tid >> 4, tc = tid & 15;

    const int k_begin = split * 128;
    const int k_end   = (k_begin + 128 < 1040) ? (k_begin + 128) : 1040;

    float acc[4][4];
#pragma unroll
    for (int i = 0; i < 4; i++)
#pragma unroll
        for (int j = 0; j < 4; j++) acc[i][j] = 0.f;

    for (int kb = k_begin; kb < k_end; kb += 16) {
#pragma unroll
        for (int l = 0; l < 4; l++) {
            int idx = tid + l * 256;
            int kk = idx & 15;
            int m  = idx >> 4;
            int k  = kb + kk;
            int b = row0 + m;
            float av = 0.f;
            if (b < NB) av = (k < NI) ? x[b * NI + k] : z[b * NR + (k - NI)];
            As[kk][m] = av;
            int r = col0 + m;
            float wv;
            if (k < NI) {
                wv = w_in[r * NI + k];
            } else {
                int kr = k - NI;
                wv = (kr == r) ? 0.f : w_rec[r * NR + kr];
            }
            Ws[kk][m] = wv;
        }
        __syncthreads();
#pragma unroll
        for (int kk = 0; kk < 16; kk++) {
            const float4 ra = *(const float4*)&As[kk][tr * 4];   // LDS.128
            const float4 rb = *(const float4*)&Ws[kk][tc * 4];   // LDS.128
            acc[0][0] = fmaf(ra.x, rb.x, acc[0][0]); acc[0][1] = fmaf(ra.x, rb.y, acc[0][1]);
            acc[0][2] = fmaf(ra.x, rb.z, acc[0][2]); acc[0][3] = fmaf(ra.x, rb.w, acc[0][3]);
            acc[1][0] = fmaf(ra.y, rb.x, acc[1][0]); acc[1][1] = fmaf(ra.y, rb.y, acc[1][1]);
            acc[1][2] = fmaf(ra.y, rb.z, acc[1][2]); acc[1][3] = fmaf(ra.y, rb.w, acc[1][3]);
            acc[2][0] = fmaf(ra.z, rb.x, acc[2][0]); acc[2][1] = fmaf(ra.z, rb.y, acc[2][1]);
            acc[2][2] = fmaf(ra.z, rb.z, acc[2][2]); acc[2][3] = fmaf(ra.z, rb.w, acc[2][3]);
            acc[3][0] = fmaf(ra.w, rb.x, acc[3][0]); acc[3][1] = fmaf(ra.w, rb.y, acc[3][1]);
            acc[3][2] = fmaf(ra.w, rb.z, acc[3][2]); acc[3][3] = fmaf(ra.w, rb.w, acc[3][3]);
        }
        __syncthreads();
    }
    float* dst = g_vpre_p + (size_t)split * NB * NR;
#pragma unroll
    for (int i = 0; i < 4; i++) {
        int b = row0 + tr * 4 + i;
        if (b < NB) {
            float4 vv = make_float4(acc[i][0], acc[i][1], acc[i][2], acc[i][3]);
            *(float4*)(dst + b * NR + col0 + tc * 4) = vv;
        }
    }
}

// ---------------- per-batch fused step ----------------
__global__ void __launch_bounds__(256)
k_step(const float* __restrict__ v, const float* __restrict__ vo,
       const float* __restrict__ z, const float* __restrict__ Faz,
       const float* __restrict__ Fkz, const float* __restrict__ Fax,
       const float* __restrict__ x, const float* __restrict__ w_out,
       const float* __restrict__ yt, float* __restrict__ yo_out) {
    const int b = blockIdx.x;
    const int r = threadIdx.x;
    __shared__ float s_zn[NR];
    __shared__ float s_tmp[NO];

    const int ir = b * NR + r;
    float vpre = 0.f;
#pragma unroll
    for (int s = 0; s < NSPLIT; s++) vpre += g_vpre_p[(size_t)s * NB * NR + ir];

    const float zb = z[ir];
    const float vn = vpre + ALPHA * v[ir] * (1.f - zb);
    const float zn = (vn > 1.f) ? 1.f : 0.f;
    s_zn[r] = zn;
    const float h = fmaxf(0.f, 1.f - fabsf(vn - 1.f));
    g_Fazn[ir] = ALPHA * Faz[ir] + zb;
    g_Fkzn[ir] = KAPPA * Fkz[ir] + zn;

    if (r < 196) {
        const float4 fx = ((const float4*)(Fax + b * NI))[r];
        const float4 xx = ((const float4*)(x + b * NI))[r];
        float4 o;
        o.x = fmaf(ALPHA, fx.x, xx.x);
        o.y = fmaf(ALPHA, fx.y, xx.y);
        o.z = fmaf(ALPHA, fx.z, xx.z);
        o.w = fmaf(ALPHA, fx.w, xx.w);
        ((float4*)(g_Faxn + b * NI))[r] = o;
    }
    __syncthreads();

    if (r < NO) {
        float a = KAPPA * vo[b * NO + r];
#pragma unroll 8
        for (int j = 0; j < NR; j++) a = fmaf(s_zn[j], w_out[r * NR + j], a);
        s_tmp[r] = a;
    }
    __syncthreads();

    if (r == 0) {
        float m = s_tmp[0];
#pragma unroll
        for (int o = 1; o < NO; o++) m = fmaxf(m, s_tmp[o]);
        float e[NO];
        float s = 0.f;
#pragma unroll
        for (int o = 0; o < NO; o++) { e[o] = expf(s_tmp[o] - m); s += e[o]; }
        const float inv = 1.f / s;
#pragma unroll
        for (int o = 0; o < NO; o++) {
            const float yo = e[o] * inv;
            yo_out[b * NO + o] = yo;
            const float er = yo - yt[b * NO + o];
            s_tmp[o] = er;
            g_err[b * NO + o] = er;
        }
    }
    __syncthreads();

    float L = 0.f;
#pragma unroll
    for (int o = 0; o < NO; o++) L = fmaf(s_tmp[o], w_out[o * NR + r], L);
    g_kL[ir] = KAPPA * L;
    g_Lh[ir] = L * h;
}

// ================= MEGA KERNEL =================
// Roles (Bresenham-interleaved, period 16 = 5 special + 11 stream):
//   special: 544 outer-GEMM blocks (split-b 8) + 50 gwout blocks  (594)
//   stream : 1024 gwin blocks + 256 gwrec blocks                   (1280)
#define N_OUTER 544
#define N_SPECIAL 594
#define N_GWIN 1024
#define N_STREAM 1280
#define MEGA_GRID 1920

__device__ __forceinline__ void do_outer(int oid, float* smem,
                                         float* __restrict__ gwin,
                                         float* __restrict__ gwrec) {
    // O[i,jj] = sum_b Lh[b,i] * C[b,jj],  C = [Faxn(784) | Fazn(256)]
    float (*As)[68] = (float(*)[68])smem;
    float (*Bs)[68] = (float(*)[68])(smem + 1088);
    const int split = oid / 68;            // 0..7, b-chunks of 125
    const int rem   = oid % 68;
    const int i0 = (rem & 3) * 64;
    const int j0 = (rem >> 2) * 64;
    const int kb0 = split * 125;
    const int kb1 = kb0 + 125;
    const int tid = threadIdx.x;
    const int tr = tid >> 4, tc = tid & 15;

    float acc[4][4];
#pragma unroll
    for (int i = 0; i < 4; i++)
#pragma unroll
        for (int j = 0; j < 4; j++) acc[i][j] = 0.f;

    for (int kb = kb0; kb < kb1; kb += 16) {
#pragma unroll
        for (int l = 0; l < 4; l++) {
            int idx = tid + l * 256;
            int kk = idx >> 6;
            int m  = idx & 63;
            int k  = kb + kk;
            As[kk][m] = (k < kb1) ? g_Lh[k * NR + i0 + m] : 0.f;
            int jj = j0 + m;
            float bv = 0.f;
            if (k < kb1 && jj < 1040)
                bv = (jj < NI) ? g_Faxn[k * NI + jj] : g_Fazn[k * NR + (jj - NI)];
            Bs[kk][m] = bv;
        }
        __syncthreads();
#pragma unroll
        for (int kk = 0; kk < 16; kk++) {
            const float4 ra = *(const float4*)&As[kk][tr * 4];   // LDS.128
            const float4 rb = *(const float4*)&Bs[kk][tc * 4];   // LDS.128
            acc[0][0] = fmaf(ra.x, rb.x, acc[0][0]); acc[0][1] = fmaf(ra.x, rb.y, acc[0][1]);
            acc[0][2] = fmaf(ra.x, rb.z, acc[0][2]); acc[0][3] = fmaf(ra.x, rb.w, acc[0][3]);
            acc[1][0] = fmaf(ra.y, rb.x, acc[1][0]); acc[1][1] = fmaf(ra.y, rb.y, acc[1][1]);
            acc[1][2] = fmaf(ra.y, rb.z, acc[1][2]); acc[1][3] = fmaf(ra.y, rb.w, acc[1][3]);
            acc[2][0] = fmaf(ra.z, rb.x, acc[2][0]); acc[2][1] = fmaf(ra.z, rb.y, acc[2][1]);
            acc[2][2] = fmaf(ra.z, rb.z, acc[2][2]); acc[2][3] = fmaf(ra.z, rb.w, acc[2][3]);
            acc[3][0] = fmaf(ra.w, rb.x, acc[3][0]); acc[3][1] = fmaf(ra.w, rb.y, acc[3][1]);
            acc[3][2] = fmaf(ra.w, rb.z, acc[3][2]); acc[3][3] = fmaf(ra.w, rb.w, acc[3][3]);
        }
        __syncthreads();
    }
#pragma unroll
    for (int i = 0; i < 4; i++) {
        int row = i0 + tr * 4 + i;
#pragma unroll
        for (int j = 0; j < 4; j++) {
            int jj = j0 + tc * 4 + j;
            if (jj < NI)            atomicAdd(&gwin[row * NI + jj], acc[i][j]);
            else if (jj < NI + NR)  atomicAdd(&gwrec[row * NR + (jj - NI)], acc[i][j]);
        }
    }
}

__device__ __forceinline__ void do_gwout(int cid, float* smem, float* __restrict__ gwout) {
    float* s_err = smem;
    const int r = threadIdx.x;
    const int b0 = cid * 20;
    for (int t = r; t < 20 * NO; t += 256) s_err[t] = g_err[b0 * NO + t];
    __syncthreads();
    float acc[NO];
#pragma unroll
    for (int o = 0; o < NO; o++) acc[o] = 0.f;
    for (int bb = 0; bb < 20; bb++) {
        const float f = g_Fkzn[(b0 + bb) * NR + r];
#pragma unroll
        for (int o = 0; o < NO; o++) acc[o] = fmaf(s_err[bb * NO + o], f, acc[o]);
    }
#pragma unroll
    for (int o = 0; o < NO; o++) atomicAdd(&gwout[o * NR + r], acc[o]);
}

#define FMA4(A, C, F) \
    A.x = fmaf(C, F.x, A.x); A.y = fmaf(C, F.y, A.y); \
    A.z = fmaf(C, F.z, A.z); A.w = fmaf(C, F.w, A.w);

__device__ __forceinline__ void do_gwin(int sid, float* smem,
                                        const float* __restrict__ Fke_in,
                                        float* __restrict__ gwin) {
    float* s_kL = smem;
    const int t = threadIdx.x;
    const int i  = sid & 255;
    const int b0 = (sid >> 8) * 250;
    for (int tt = t; tt < 250; tt += 256) s_kL[tt] = g_kL[(b0 + tt) * NR + i];
    __syncthreads();
    if (t >= 196) return;

    const float4* fke = (const float4*)(Fke_in + ((size_t)b0 * NR + i) * NI) + t;
    const size_t stride = (size_t)NR * NI / 4;
    float4 a0 = make_float4(0.f, 0.f, 0.f, 0.f);
    float4 a1 = make_float4(0.f, 0.f, 0.f, 0.f);
    float4 a2 = make_float4(0.f, 0.f, 0.f, 0.f);
    float4 a3 = make_float4(0.f, 0.f, 0.f, 0.f);
#pragma unroll 1
    for (int bb = 0; bb < 248; bb += 4) {
        float4 f0 = __ldcs(fke + (size_t)(bb + 0) * stride);
        float4 f1 = __ldcs(fke + (size_t)(bb + 1) * stride);
        float4 f2 = __ldcs(fke + (size_t)(bb + 2) * stride);
        float4 f3 = __ldcs(fke + (size_t)(bb + 3) * stride);
        float c0 = s_kL[bb], c1 = s_kL[bb + 1], c2 = s_kL[bb + 2], c3 = s_kL[bb + 3];
        FMA4(a0, c0, f0) FMA4(a1, c1, f1) FMA4(a2, c2, f2) FMA4(a3, c3, f3)
    }
    {
        float4 f0 = __ldcs(fke + (size_t)248 * stride);
        float4 f1 = __ldcs(fke + (size_t)249 * stride);
        float c0 = s_kL[248], c1 = s_kL[249];
        FMA4(a0, c0, f0) FMA4(a1, c1, f1)
    }
    float* dst = gwin + i * NI + t * 4;
    atomicAdd(dst + 0, (a0.x + a1.x) + (a2.x + a3.x));
    atomicAdd(dst + 1, (a0.y + a1.y) + (a2.y + a3.y));
    atomicAdd(dst + 2, (a0.z + a1.z) + (a2.z + a3.z));
    atomicAdd(dst + 3, (a0.w + a1.w) + (a2.w + a3.w));
}

__device__ __forceinline__ void do_gwrec(int sid, float* smem,
                                         const float* __restrict__ Fke_rec,
                                         float* __restrict__ gwrec) {
    float* s_kL = smem;   // 1000 floats (4 rows x 250)
    const int t = threadIdx.x;
    const int i0 = (sid & 63) * 4;
    const int b0 = (sid >> 6) * 250;
    const int li = t >> 6;
    const int jv = t & 63;
    for (int tt = t; tt < 1000; tt += 256) {
        int lr = tt / 250, bb = tt % 250;
        s_kL[lr * 250 + bb] = g_kL[(b0 + bb) * NR + i0 + lr];
    }
    __syncthreads();

    const int i = i0 + li;
    const float4* fke = (const float4*)(Fke_rec + ((size_t)b0 * NR + i) * NR) + jv;
    const size_t stride = (size_t)NR * NR / 4;
    const float* kl = s_kL + li * 250;
    float4 a0 = make_float4(0.f, 0.f, 0.f, 0.f);
    float4 a1 = make_float4(0.f, 0.f, 0.f, 0.f);
    float4 a2 = make_float4(0.f, 0.f, 0.f, 0.f);
    float4 a3 = make_float4(0.f, 0.f, 0.f, 0.f);
#pragma unroll 1
    for (int bb = 0; bb < 248; bb += 4) {
        float4 f0 = __ldcs(fke + (size_t)(bb + 0) * stride);
        float4 f1 = __ldcs(fke + (size_t)(bb + 1) * stride);
        float4 f2 = __ldcs(fke + (size_t)(bb + 2) * stride);
        float4 f3 = __ldcs(fke + (size_t)(bb + 3) * stride);
        float c0 = kl[bb], c1 = kl[bb + 1], c2 = kl[bb + 2], c3 = kl[bb + 3];
        FMA4(a0, c0, f0) FMA4(a1, c1, f1) FMA4(a2, c2, f2) FMA4(a3, c3, f3)
    }
    {
        float4 f0 = __ldcs(fke + (size_t)248 * stride);
        float4 f1 = __ldcs(fke + (size_t)249 * stride);
        float c0 = kl[248], c1 = kl[249];
        FMA4(a0, c0, f0) FMA4(a1, c1, f1)
    }
    float* dst = gwrec + i * NR + jv * 4;
    atomicAdd(dst + 0, (a0.x + a1.x) + (a2.x + a3.x));
    atomicAdd(dst + 1, (a0.y + a1.y) + (a2.y + a3.y));
    atomicAdd(dst + 2, (a0.z + a1.z) + (a2.z + a3.z));
    atomicAdd(dst + 3, (a0.w + a1.w) + (a2.w + a3.w));
}

__global__ void __launch_bounds__(256)
k_mega(const float* __restrict__ Fke_in, const float* __restrict__ Fke_rec,
       float* __restrict__ gwin, float* __restrict__ gwrec, float* __restrict__ gwout) {
    __shared__ __align__(16) float smem[2176];
    const int p = blockIdx.x >> 4;
    const int l = blockIdx.x & 15;
    if (l < 5) {
        int sid = p * 5 + l;
        if (sid >= N_SPECIAL) return;
        if (sid < N_OUTER) do_outer(sid, smem, gwin, gwrec);
        else               do_gwout(sid - N_OUTER, smem, gwout);
    } else {
        int sid = p * 11 + (l - 5);
        if (sid >= N_STREAM) return;
        if (sid < N_GWIN) do_gwin(sid, smem, Fke_in, gwin);
        else              do_gwrec(sid - N_GWIN, smem, Fke_rec, gwrec);
    }
}

// ---------------- launch ----------------
extern "C" void kernel_launch(void* const* d_in, const int* in_sizes, int n_in,
                              void* d_out, int out_size) {
    const float* x       = (const float*)d_in[0];
    const float* yt      = (const float*)d_in[2];
    const float* w_in    = (const float*)d_in[3];
    const float* w_rec   = (const float*)d_in[4];
    const float* w_out   = (const float*)d_in[5];
    const float* v       = (const float*)d_in[6];
    const float* vo      = (const float*)d_in[7];
    const float* z       = (const float*)d_in[8];
    const float* Faz     = (const float*)d_in[9];
    const float* Fkz     = (const float*)d_in[10];
    const float* Fax     = (const float*)d_in[11];
    const float* Fke_rec = (const float*)d_in[12];
    const float* Fke_in  = (const float*)d_in[13];

    float* out     = (float*)d_out;
    float* yo_o    = out;
    float* gwin_o  = out + NB * NO;
    float* gwrec_o = gwin_o + NR * NI;
    float* gwout_o = gwrec_o + NR * NR;

    k_prep<<<PREP_GRID, 256>>>(x, z, w_in, w_rec, gwin_o, gwrec_o, gwout_o);
    k_step<<<NB, NR>>>(v, vo, z, Faz, Fkz, Fax, x, w_out, yt, yo_o);
    k_mega<<<MEGA_GRID, 256>>>(Fke_in, Fke_rec, gwin_o, gwrec_o, gwout_o);
}

// round 7
// speedup vs baseline: 2.0663x; 1.0732x over previous
#include <cuda_runtime.h>

// Problem dims
#define NB 1000
#define NI 784
#define NR 256
#define NO 10

#define ALPHA 0.8f
#define KAPPA 0.8f

#define NSPLIT 9           // gemm split-K count (chunks of 128 over K=1040)

// ---------------- scratch (__device__ globals; no allocation) ----------------
__device__ float g_vpre_p[NSPLIT * NB * NR];  // split-K partials (no atomics)
__device__ float g_kL  [NB * NR];
__device__ float g_Lh  [NB * NR];
__device__ float g_Fazn[NB * NR];
__device__ float g_Fkzn[NB * NR];
__device__ float g_Faxn[NB * NI];
__device__ float g_err [NB * NO];

// ================= PREP KERNEL: gemm tiles + output zeroing in one launch =================
// blocks [0,576): vpre split-K GEMM tiles;  blocks [576,592): zero gwin/gwrec/gwout
#define N_GEMM 576
#define PREP_GRID 592      // exactly 4 waves on 148 SMs

__global__ void __launch_bounds__(256)
k_prep(const float* __restrict__ x, const float* __restrict__ z,
       const float* __restrict__ w_in, const float* __restrict__ w_rec,
       float* __restrict__ gwin, float* __restrict__ gwrec, float* __restrict__ gwout) {
    if (blockIdx.x >= N_GEMM) {
        int idx = (blockIdx.x - N_GEMM) * 256 + threadIdx.x;
        int stride = (PREP_GRID - N_GEMM) * 256;
        for (int i = idx; i < NR * NI; i += stride) gwin[i] = 0.f;
        for (int i = idx; i < NR * NR; i += stride) gwrec[i] = 0.f;
        for (int i = idx; i < NO * NR; i += stride) gwout[i] = 0.f;
        return;
    }
    // ---- GEMM role: vpre_p[s][b,r] = sum_{k in chunk s} A[b,k] * W[r,k] ----
    // A = [x | z] (K=1040), W = [w_in | w_rec(diag zeroed)]
    __shared__ __align__(16) float As[16][68];
    __shared__ __align__(16) float Ws[16][68];
    const int bi = blockIdx.x;
    const int split = bi >> 6;           // 0..8
    const int rem   = bi & 63;
    const int row0 = (rem & 15) * 64;    // batch tile
    const int col0 = (rem >> 4) * 64;    // rec-unit tile
    const int tid = threadIdx.x;
    const int tr = tid >> 4, tc = tid & 15;
    const int kk_l = tid & 15;           // loader k-offset (coalesced across lanes)
    const int m_l  = tid >> 4;           // loader m base (+16 per l)

    const int k_begin = split * 128;
    const int k_end   = (k_begin + 128 < 1040) ? (k_begin + 128) : 1040;

    float avp[4], wvp[4];
    // prefetch first tile into registers
    {
        const int kb = k_begin;
#pragma unroll
        for (int l = 0; l < 4; l++) {
            int m = m_l + l * 16;
            int k = kb + kk_l;
            int b = row0 + m;
            float av = 0.f;
            if (b < NB) av = (k < NI) ? x[b * NI + k] : z[b * NR + (k - NI)];
            avp[l] = av;
            int r = col0 + m;
            if (k < NI) wvp[l] = w_in[r * NI + k];
            else { int kr = k - NI; wvp[l] = (kr == r) ? 0.f : w_rec[r * NR + kr]; }
        }
    }

    float acc[4][4];
#pragma unroll
    for (int i = 0; i < 4; i++)
#pragma unroll
        for (int j = 0; j < 4; j++) acc[i][j] = 0.f;

    for (int kb = k_begin; kb < k_end; kb += 16) {
        // commit prefetched tile to smem
#pragma unroll
        for (int l = 0; l < 4; l++) {
            As[kk_l][m_l + l * 16] = avp[l];
            Ws[kk_l][m_l + l * 16] = wvp[l];
        }
        __syncthreads();
        // issue next tile's loads (overlap with compute)
        if (kb + 16 < k_end) {
            const int kn = kb + 16;
#pragma unroll
            for (int l = 0; l < 4; l++) {
                int m = m_l + l * 16;
                int k = kn + kk_l;
                int b = row0 + m;
                float av = 0.f;
                if (b < NB) av = (k < NI) ? x[b * NI + k] : z[b * NR + (k - NI)];
                avp[l] = av;
                int r = col0 + m;
                if (k < NI) wvp[l] = w_in[r * NI + k];
                else { int kr = k - NI; wvp[l] = (kr == r) ? 0.f : w_rec[r * NR + kr]; }
            }
        }
#pragma unroll
        for (int kk = 0; kk < 16; kk++) {
            const float4 ra = *(const float4*)&As[kk][tr * 4];   // LDS.128
            const float4 rb = *(const float4*)&Ws[kk][tc * 4];   // LDS.128
            acc[0][0] = fmaf(ra.x, rb.x, acc[0][0]); acc[0][1] = fmaf(ra.x, rb.y, acc[0][1]);
            acc[0][2] = fmaf(ra.x, rb.z, acc[0][2]); acc[0][3] = fmaf(ra.x, rb.w, acc[0][3]);
            acc[1][0] = fmaf(ra.y, rb.x, acc[1][0]); acc[1][1] = fmaf(ra.y, rb.y, acc[1][1]);
            acc[1][2] = fmaf(ra.y, rb.z, acc[1][2]); acc[1][3] = fmaf(ra.y, rb.w, acc[1][3]);
            acc[2][0] = fmaf(ra.z, rb.x, acc[2][0]); acc[2][1] = fmaf(ra.z, rb.y, acc[2][1]);
            acc[2][2] = fmaf(ra.z, rb.z, acc[2][2]); acc[2][3] = fmaf(ra.z, rb.w, acc[2][3]);
            acc[3][0] = fmaf(ra.w, rb.x, acc[3][0]); acc[3][1] = fmaf(ra.w, rb.y, acc[3][1]);
            acc[3][2] = fmaf(ra.w, rb.z, acc[3][2]); acc[3][3] = fmaf(ra.w, rb.w, acc[3][3]);
        }
        __syncthreads();
    }
    float* dst = g_vpre_p + (size_t)split * NB * NR;
#pragma unroll
    for (int i = 0; i < 4; i++) {
        int b = row0 + tr * 4 + i;
        if (b < NB) {
            float4 vv = make_float4(acc[i][0], acc[i][1], acc[i][2], acc[i][3]);
            *(float4*)(dst + b * NR + col0 + tc * 4) = vv;
        }
    }
}

// ---------------- per-batch fused step ----------------
__global__ void __launch_bounds__(256)
k_step(const float* __restrict__ v, const float* __restrict__ vo,
       const float* __restrict__ z, const float* __restrict__ Faz,
       const float* __restrict__ Fkz, const float* __restrict__ Fax,
       const float* __restrict__ x, const float* __restrict__ w_out,
       const float* __restrict__ yt, float* __restrict__ yo_out) {
    const int b = blockIdx.x;
    const int r = threadIdx.x;
    __shared__ float s_zn[NR];
    __shared__ float s_err[NO];

    const int ir = b * NR + r;
    float vpre = 0.f;
#pragma unroll
    for (int s = 0; s < NSPLIT; s++) vpre += g_vpre_p[(size_t)s * NB * NR + ir];

    const float zb = z[ir];
    const float vn = vpre + ALPHA * v[ir] * (1.f - zb);
    const float zn = (vn > 1.f) ? 1.f : 0.f;
    s_zn[r] = zn;
    const float h = fmaxf(0.f, 1.f - fabsf(vn - 1.f));
    g_Fazn[ir] = ALPHA * Faz[ir] + zb;
    g_Fkzn[ir] = KAPPA * Fkz[ir] + zn;

    if (r < 196) {
        const float4 fx = ((const float4*)(Fax + b * NI))[r];
        const float4 xx = ((const float4*)(x + b * NI))[r];
        float4 o;
        o.x = fmaf(ALPHA, fx.x, xx.x);
        o.y = fmaf(ALPHA, fx.y, xx.y);
        o.z = fmaf(ALPHA, fx.z, xx.z);
        o.w = fmaf(ALPHA, fx.w, xx.w);
        ((float4*)(g_Faxn + b * NI))[r] = o;
    }
    __syncthreads();

    // vo_new GEMV in warp 0 (lanes split r, shfl-reduce), softmax in lane 0 regs
    if (r < 32) {
        const int lane = r;
        float part[NO];
#pragma unroll
        for (int o = 0; o < NO; o++) {
            float p = 0.f;
#pragma unroll
            for (int k = 0; k < 8; k++)
                p = fmaf(s_zn[lane + 32 * k], w_out[o * NR + lane + 32 * k], p);
#pragma unroll
            for (int off = 16; off; off >>= 1) p += __shfl_xor_sync(0xffffffffu, p, off);
            part[o] = p;   // full sum in all lanes
        }
        if (lane == 0) {
            float vn_o[NO];
            float m = -1e30f;
#pragma unroll
            for (int o = 0; o < NO; o++) {
                vn_o[o] = KAPPA * vo[b * NO + o] + part[o];
                m = fmaxf(m, vn_o[o]);
            }
            float e[NO], s = 0.f;
#pragma unroll
            for (int o = 0; o < NO; o++) { e[o] = expf(vn_o[o] - m); s += e[o]; }
            const float inv = 1.f / s;
#pragma unroll
            for (int o = 0; o < NO; o++) {
                const float yo = e[o] * inv;
                yo_out[b * NO + o] = yo;
                const float er = yo - yt[b * NO + o];
                s_err[o] = er;
                g_err[b * NO + o] = er;
            }
        }
    }
    __syncthreads();

    float L = 0.f;
#pragma unroll
    for (int o = 0; o < NO; o++) L = fmaf(s_err[o], w_out[o * NR + r], L);
    g_kL[ir] = KAPPA * L;
    g_Lh[ir] = L * h;
}

// ================= MEGA KERNEL =================
// Roles (Bresenham-interleaved, period 5 = 1 special + 4 stream):
//   special: 272 outer-GEMM blocks (4 b-splits of 250) + 50 gwout   (322)
//   stream : 1024 gwin blocks + 256 gwrec blocks                    (1280)
#define N_OUTER 272
#define N_SPECIAL 322
#define N_GWIN 1024
#define N_STREAM 1280
#define MEGA_GRID 1610     // 322 periods of 5

__device__ __forceinline__ void do_outer(int oid, float* smem,
                                         float* __restrict__ gwin,
                                         float* __restrict__ gwrec) {
    // O[i,jj] = sum_b Lh[b,i] * C[b,jj],  C = [Faxn(784) | Fazn(256)]
    float (*As)[68] = (float(*)[68])smem;
    float (*Bs)[68] = (float(*)[68])(smem + 1088);
    const int split = oid / 68;            // 0..3, b-chunks of 250
    const int rem   = oid % 68;
    const int i0 = (rem & 3) * 64;
    const int j0 = (rem >> 2) * 64;
    const int kb0 = split * 250;
    const int kb1 = kb0 + 250;
    const int tid = threadIdx.x;
    const int tr = tid >> 4, tc = tid & 15;

    float acc[4][4];
#pragma unroll
    for (int i = 0; i < 4; i++)
#pragma unroll
        for (int j = 0; j < 4; j++) acc[i][j] = 0.f;

    for (int kb = kb0; kb < kb1; kb += 16) {
#pragma unroll
        for (int l = 0; l < 4; l++) {
            int idx = tid + l * 256;
            int kk = idx >> 6;
            int m  = idx & 63;       // consecutive lanes -> consecutive i/jj (coalesced)
            int k  = kb + kk;
            As[kk][m] = (k < kb1) ? g_Lh[k * NR + i0 + m] : 0.f;
            int jj = j0 + m;
            float bv = 0.f;
            if (k < kb1 && jj < 1040)
                bv = (jj < NI) ? g_Faxn[k * NI + jj] : g_Fazn[k * NR + (jj - NI)];
            Bs[kk][m] = bv;
        }
        __syncthreads();
#pragma unroll
        for (int kk = 0; kk < 16; kk++) {
            const float4 ra = *(const float4*)&As[kk][tr * 4];   // LDS.128
            const float4 rb = *(const float4*)&Bs[kk][tc * 4];   // LDS.128
            acc[0][0] = fmaf(ra.x, rb.x, acc[0][0]); acc[0][1] = fmaf(ra.x, rb.y, acc[0][1]);
            acc[0][2] = fmaf(ra.x, rb.z, acc[0][2]); acc[0][3] = fmaf(ra.x, rb.w, acc[0][3]);
            acc[1][0] = fmaf(ra.y, rb.x, acc[1][0]); acc[1][1] = fmaf(ra.y, rb.y, acc[1][1]);
            acc[1][2] = fmaf(ra.y, rb.z, acc[1][2]); acc[1][3] = fmaf(ra.y, rb.w, acc[1][3]);
            acc[2][0] = fmaf(ra.z, rb.x, acc[2][0]); acc[2][1] = fmaf(ra.z, rb.y, acc[2][1]);
            acc[2][2] = fmaf(ra.z, rb.z, acc[2][2]); acc[2][3] = fmaf(ra.z, rb.w, acc[2][3]);
            acc[3][0] = fmaf(ra.w, rb.x, acc[3][0]); acc[3][1] = fmaf(ra.w, rb.y, acc[3][1]);
            acc[3][2] = fmaf(ra.w, rb.z, acc[3][2]); acc[3][3] = fmaf(ra.w, rb.w, acc[3][3]);
        }
        __syncthreads();
    }
#pragma unroll
    for (int i = 0; i < 4; i++) {
        int row = i0 + tr * 4 + i;
#pragma unroll
        for (int j = 0; j < 4; j++) {
            int jj = j0 + tc * 4 + j;
            if (jj < NI)            atomicAdd(&gwin[row * NI + jj], acc[i][j]);
            else if (jj < NI + NR)  atomicAdd(&gwrec[row * NR + (jj - NI)], acc[i][j]);
        }
    }
}

__device__ __forceinline__ void do_gwout(int cid, float* smem, float* __restrict__ gwout) {
    float* s_err = smem;
    const int r = threadIdx.x;
    const int b0 = cid * 20;
    for (int t = r; t < 20 * NO; t += 256) s_err[t] = g_err[b0 * NO + t];
    __syncthreads();
    float acc[NO];
#pragma unroll
    for (int o = 0; o < NO; o++) acc[o] = 0.f;
    for (int bb = 0; bb < 20; bb++) {
        const float f = g_Fkzn[(b0 + bb) * NR + r];
#pragma unroll
        for (int o = 0; o < NO; o++) acc[o] = fmaf(s_err[bb * NO + o], f, acc[o]);
    }
#pragma unroll
    for (int o = 0; o < NO; o++) atomicAdd(&gwout[o * NR + r], acc[o]);
}

#define FMA4(A, C, F) \
    A.x = fmaf(C, F.x, A.x); A.y = fmaf(C, F.y, A.y); \
    A.z = fmaf(C, F.z, A.z); A.w = fmaf(C, F.w, A.w);

__device__ __forceinline__ void do_gwin(int sid, float* smem,
                                        const float* __restrict__ Fke_in,
                                        float* __restrict__ gwin) {
    float* s_kL = smem;
    const int t = threadIdx.x;
    const int i  = sid & 255;
    const int b0 = (sid >> 8) * 250;
    for (int tt = t; tt < 250; tt += 256) s_kL[tt] = g_kL[(b0 + tt) * NR + i];
    __syncthreads();
    if (t >= 196) return;

    const float4* fke = (const float4*)(Fke_in + ((size_t)b0 * NR + i) * NI) + t;
    const size_t stride = (size_t)NR * NI / 4;
    float4 a0 = make_float4(0.f, 0.f, 0.f, 0.f);
    float4 a1 = make_float4(0.f, 0.f, 0.f, 0.f);
    float4 a2 = make_float4(0.f, 0.f, 0.f, 0.f);
    float4 a3 = make_float4(0.f, 0.f, 0.f, 0.f);
#pragma unroll 1
    for (int bb = 0; bb < 248; bb += 4) {
        float4 f0 = __ldcs(fke + (size_t)(bb + 0) * stride);
        float4 f1 = __ldcs(fke + (size_t)(bb + 1) * stride);
        float4 f2 = __ldcs(fke + (size_t)(bb + 2) * stride);
        float4 f3 = __ldcs(fke + (size_t)(bb + 3) * stride);
        float c0 = s_kL[bb], c1 = s_kL[bb + 1], c2 = s_kL[bb + 2], c3 = s_kL[bb + 3];
        FMA4(a0, c0, f0) FMA4(a1, c1, f1) FMA4(a2, c2, f2) FMA4(a3, c3, f3)
    }
    {
        float4 f0 = __ldcs(fke + (size_t)248 * stride);
        float4 f1 = __ldcs(fke + (size_t)249 * stride);
        float c0 = s_kL[248], c1 = s_kL[249];
        FMA4(a0, c0, f0) FMA4(a1, c1, f1)
    }
    float* dst = gwin + i * NI + t * 4;
    atomicAdd(dst + 0, (a0.x + a1.x) + (a2.x + a3.x));
    atomicAdd(dst + 1, (a0.y + a1.y) + (a2.y + a3.y));
    atomicAdd(dst + 2, (a0.z + a1.z) + (a2.z + a3.z));
    atomicAdd(dst + 3, (a0.w + a1.w) + (a2.w + a3.w));
}

__device__ __forceinline__ void do_gwrec(int sid, float* smem,
                                         const float* __restrict__ Fke_rec,
                                         float* __restrict__ gwrec) {
    float* s_kL = smem;   // 1000 floats (4 rows x 250)
    const int t = threadIdx.x;
    const int i0 = (sid & 63) * 4;
    const int b0 = (sid >> 6) * 250;
    const int li = t >> 6;
    const int jv = t & 63;
    for (int tt = t; tt < 1000; tt += 256) {
        int lr = tt / 250, bb = tt % 250;
        s_kL[lr * 250 + bb] = g_kL[(b0 + bb) * NR + i0 + lr];
    }
    __syncthreads();

    const int i = i0 + li;
    const float4* fke = (const float4*)(Fke_rec + ((size_t)b0 * NR + i) * NR) + jv;
    const size_t stride = (size_t)NR * NR / 4;
    const float* kl = s_kL + li * 250;
    float4 a0 = make_float4(0.f, 0.f, 0.f, 0.f);
    float4 a1 = make_float4(0.f, 0.f, 0.f, 0.f);
    float4 a2 = make_float4(0.f, 0.f, 0.f, 0.f);
    float4 a3 = make_float4(0.f, 0.f, 0.f, 0.f);
#pragma unroll 1
    for (int bb = 0; bb < 248; bb += 4) {
        float4 f0 = __ldcs(fke + (size_t)(bb + 0) * stride);
        float4 f1 = __ldcs(fke + (size_t)(bb + 1) * stride);
        float4 f2 = __ldcs(fke + (size_t)(bb + 2) * stride);
        float4 f3 = __ldcs(fke + (size_t)(bb + 3) * stride);
        float c0 = kl[bb], c1 = kl[bb + 1], c2 = kl[bb + 2], c3 = kl[bb + 3];
        FMA4(a0, c0, f0) FMA4(a1, c1, f1) FMA4(a2, c2, f2) FMA4(a3, c3, f3)
    }
    {
        float4 f0 = __ldcs(fke + (size_t)248 * stride);
        float4 f1 = __ldcs(fke + (size_t)249 * stride);
        float c0 = kl[248], c1 = kl[249];
        FMA4(a0, c0, f0) FMA4(a1, c1, f1)
    }
    float* dst = gwrec + i * NR + jv * 4;
    atomicAdd(dst + 0, (a0.x + a1.x) + (a2.x + a3.x));
    atomicAdd(dst + 1, (a0.y + a1.y) + (a2.y + a3.y));
    atomicAdd(dst + 2, (a0.z + a1.z) + (a2.z + a3.z));
    atomicAdd(dst + 3, (a0.w + a1.w) + (a2.w + a3.w));
}

__global__ void __launch_bounds__(256)
k_mega(const float* __restrict__ Fke_in, const float* __restrict__ Fke_rec,
       float* __restrict__ gwin, float* __restrict__ gwrec, float* __restrict__ gwout) {
    __shared__ __align__(16) float smem[2176];
    const int p = blockIdx.x / 5;
    const int l = blockIdx.x % 5;
    if (l == 0) {
        int sid = p;
        if (sid >= N_SPECIAL) return;
        if (sid < N_OUTER) do_outer(sid, smem, gwin, gwrec);
        else               do_gwout(sid - N_OUTER, smem, gwout);
    } else {
        int sid = p * 4 + (l - 1);
        if (sid >= N_STREAM) return;
        if (sid < N_GWIN) do_gwin(sid, smem, Fke_in, gwin);
        else              do_gwrec(sid - N_GWIN, smem, Fke_rec, gwrec);
    }
}

// ---------------- launch ----------------
extern "C" void kernel_launch(void* const* d_in, const int* in_sizes, int n_in,
                              void* d_out, int out_size) {
    const float* x       = (const float*)d_in[0];
    const float* yt      = (const float*)d_in[2];
    const float* w_in    = (const float*)d_in[3];
    const float* w_rec   = (const float*)d_in[4];
    const float* w_out   = (const float*)d_in[5];
    const float* v       = (const float*)d_in[6];
    const float* vo      = (const float*)d_in[7];
    const float* z       = (const float*)d_in[8];
    const float* Faz     = (const float*)d_in[9];
    const float* Fkz     = (const float*)d_in[10];
    const float* Fax     = (const float*)d_in[11];
    const float* Fke_rec = (const float*)d_in[12];
    const float* Fke_in  = (const float*)d_in[13];

    float* out     = (float*)d_out;
    float* yo_o    = out;
    float* gwin_o  = out + NB * NO;
    float* gwrec_o = gwin_o + NR * NI;
    float* gwout_o = gwrec_o + NR * NR;

    k_prep<<<PREP_GRID, 256>>>(x, z, w_in, w_rec, gwin_o, gwrec_o, gwout_o);
    k_step<<<NB, NR>>>(v, vo, z, Faz, Fkz, Fax, x, w_out, yt, yo_o);
    k_mega<<<MEGA_GRID, 256>>>(Fke_in, Fke_rec, gwin_o, gwrec_o, gwout_o);
}